// round 1
// baseline (speedup 1.0000x reference)
#include <cuda_runtime.h>

static constexpr int B_   = 2;
static constexpr int VL_  = 2048;
static constexpr int TL_  = 448;
static constexpr int KL_  = 64;
static constexpr int TOT_ = 2560;   // VL+TL+KL
static constexpr int MID_ = 2496;   // VL+TL
static constexpr int H_   = 1024;
static constexpr int NH_  = 16;
static constexpr int D_   = 64;

// ---------------- scratch (static device allocations) ----------------
__device__ float g_q0[B_*TOT_*H_];
__device__ float g_k0[B_*TOT_*H_];
__device__ float g_v0[B_*TOT_*H_];
__device__ float g_mid[B_*MID_*H_];
__device__ float g_q1[B_*TOT_*H_];
__device__ float g_k1[B_*TOT_*H_];
__device__ float g_v1[B_*TOT_*H_];
__device__ float g_ao[B_*TOT_*H_];

// ---------------- GEMM: C = X @ W^T + bias ----------------
// Tile 64x64, K-step 16, 256 threads, 4x4 per thread.
// GATHER=true: rows come from the 3-way concat (vision/text/task).
__device__ __forceinline__ const float* gather_row(
    const float* __restrict__ v, const float* __restrict__ t,
    const float* __restrict__ k, int r)
{
    int b   = r / TOT_;
    int tok = r - b * TOT_;
    if (tok < VL_)  return v + (size_t)(b * VL_ + tok) * H_;
    if (tok < MID_) return t + (size_t)(b * TL_ + (tok - VL_)) * H_;
    return k + (size_t)(b * KL_ + (tok - MID_)) * H_;
}

template<bool GATHER>
__global__ __launch_bounds__(256) void gemm64(
    const float* __restrict__ X, int xRowStride, long xBatch,
    const float* __restrict__ Vv, const float* __restrict__ Tt, const float* __restrict__ Kk,
    const float* __restrict__ W, const float* __restrict__ bias,
    float* __restrict__ C, long cBatch, int N, int K)
{
    __shared__ float As[16][65];
    __shared__ float Bs[16][65];
    __shared__ const float* rowp[64];

    const int tid = threadIdx.x;
    const int ty  = tid >> 4;
    const int tx  = tid & 15;
    const int m0  = blockIdx.y * 64;
    const int n0  = blockIdx.x * 64;
    const int bz  = blockIdx.z;

    if (tid < 64) {
        int m = m0 + tid;
        if (GATHER) rowp[tid] = gather_row(Vv, Tt, Kk, m);
        else        rowp[tid] = X + (long)bz * xBatch + (long)m * xRowStride;
    }
    __syncthreads();

    const int c  = tid & 15;     // k-column within tile
    const int r0 = tid >> 4;     // base row for loads

    const float* xr[4];
    const float* wr[4];
#pragma unroll
    for (int i = 0; i < 4; i++) {
        xr[i] = rowp[r0 + i * 16];
        wr[i] = W + (long)(n0 + r0 + i * 16) * K;
    }

    float acc[4][4];
#pragma unroll
    for (int i = 0; i < 4; i++)
#pragma unroll
        for (int j = 0; j < 4; j++) acc[i][j] = 0.f;

    for (int k0 = 0; k0 < K; k0 += 16) {
#pragma unroll
        for (int i = 0; i < 4; i++) {
            As[c][r0 + i * 16] = xr[i][k0 + c];
            Bs[c][r0 + i * 16] = wr[i][k0 + c];
        }
        __syncthreads();
#pragma unroll
        for (int kk = 0; kk < 16; kk++) {
            float a[4], b[4];
#pragma unroll
            for (int i = 0; i < 4; i++) a[i] = As[kk][ty * 4 + i];
#pragma unroll
            for (int j = 0; j < 4; j++) b[j] = Bs[kk][tx * 4 + j];
#pragma unroll
            for (int i = 0; i < 4; i++)
#pragma unroll
                for (int j = 0; j < 4; j++) acc[i][j] += a[i] * b[j];
        }
        __syncthreads();
    }

    float bb[4];
#pragma unroll
    for (int j = 0; j < 4; j++) bb[j] = bias[n0 + tx * 4 + j];

#pragma unroll
    for (int i = 0; i < 4; i++) {
        float4 out;
        out.x = acc[i][0] + bb[0];
        out.y = acc[i][1] + bb[1];
        out.z = acc[i][2] + bb[2];
        out.w = acc[i][3] + bb[3];
        long off = (long)bz * cBatch + (long)(m0 + ty * 4 + i) * N + n0 + tx * 4;
        *reinterpret_cast<float4*>(C + off) = out;
    }
}

// ---------------- Flash attention ----------------
// Q/K/V/O laid out as [B, tokens, NH, D] with token stride H_=NH*D.
// grid = (qlen/64, B*NH). 64 queries per block, full D=64 head dim.
static constexpr int FLASH_SMEM = 4 * 64 * 68 * (int)sizeof(float);  // 69632 B

__global__ __launch_bounds__(256) void flash_kernel(
    const float* __restrict__ Q, const float* __restrict__ K,
    const float* __restrict__ V, float* __restrict__ O,
    long bsQ, long bsK, long bsV, long bsO,
    int klen, float scale)
{
    extern __shared__ float sm[];
    float* Qs = sm;
    float* Ks = sm + 64 * 68;
    float* Vs = sm + 2 * 64 * 68;
    float* Ps = sm + 3 * 64 * 68;

    const int tid = threadIdx.x;
    const int ty  = tid >> 4;
    const int tx  = tid & 15;
    const int b   = blockIdx.y >> 4;
    const int h   = blockIdx.y & 15;

    const long qbase = (long)b * bsQ + (long)blockIdx.x * 64 * H_ + h * D_;
    // load Q tile [64 x 64]
#pragma unroll
    for (int i = 0; i < 4; i++) {
        int idx = tid + i * 256;
        int r = idx >> 4, c4 = idx & 15;
        float4 v = *reinterpret_cast<const float4*>(Q + qbase + (long)r * H_ + c4 * 4);
        reinterpret_cast<float4*>(Qs + r * 68)[c4] = v;
    }

    float m_i[4], l_i[4], o[4][4];
#pragma unroll
    for (int i = 0; i < 4; i++) {
        m_i[i] = -1e30f;
        l_i[i] = 0.f;
#pragma unroll
        for (int j = 0; j < 4; j++) o[i][j] = 0.f;
    }

    const long kbase = (long)b * bsK + h * D_;
    const long vbase = (long)b * bsV + h * D_;
    const int ntiles = klen >> 6;

    for (int kt = 0; kt < ntiles; kt++) {
        __syncthreads();   // protect Ks/Vs/Ps reuse (and Qs store on first iter)
#pragma unroll
        for (int i = 0; i < 4; i++) {
            int idx = tid + i * 256;
            int r = idx >> 4, c4 = idx & 15;
            long toff = (long)(kt * 64 + r) * H_ + c4 * 4;
            reinterpret_cast<float4*>(Ks + r * 68)[c4] =
                *reinterpret_cast<const float4*>(K + kbase + toff);
            reinterpret_cast<float4*>(Vs + r * 68)[c4] =
                *reinterpret_cast<const float4*>(V + vbase + toff);
        }
        __syncthreads();

        // S = (Q K^T) * scale ; thread owns rows ty*4.. / cols tx*4..
        float s[4][4];
#pragma unroll
        for (int i = 0; i < 4; i++)
#pragma unroll
            for (int j = 0; j < 4; j++) s[i][j] = 0.f;

#pragma unroll 8
        for (int d = 0; d < 64; d++) {
            float a[4], bb[4];
#pragma unroll
            for (int i = 0; i < 4; i++) a[i]  = Qs[(ty * 4 + i) * 68 + d];
#pragma unroll
            for (int j = 0; j < 4; j++) bb[j] = Ks[(tx * 4 + j) * 68 + d];
#pragma unroll
            for (int i = 0; i < 4; i++)
#pragma unroll
                for (int j = 0; j < 4; j++) s[i][j] += a[i] * bb[j];
        }

        float rm[4];
#pragma unroll
        for (int i = 0; i < 4; i++) {
#pragma unroll
            for (int j = 0; j < 4; j++) s[i][j] *= scale;
            rm[i] = fmaxf(fmaxf(s[i][0], s[i][1]), fmaxf(s[i][2], s[i][3]));
        }
        // reduce row-max across the 16 tx lanes (lane bits 0..3)
#pragma unroll
        for (int off = 8; off >= 1; off >>= 1)
#pragma unroll
            for (int i = 0; i < 4; i++)
                rm[i] = fmaxf(rm[i], __shfl_xor_sync(0xffffffffu, rm[i], off));

        float rs[4];
#pragma unroll
        for (int i = 0; i < 4; i++) {
            float mnew  = fmaxf(m_i[i], rm[i]);
            float alpha = __expf(m_i[i] - mnew);
            float p0 = __expf(s[i][0] - mnew);
            float p1 = __expf(s[i][1] - mnew);
            float p2 = __expf(s[i][2] - mnew);
            float p3 = __expf(s[i][3] - mnew);
            rs[i] = p0 + p1 + p2 + p3;
            float4 pv = {p0, p1, p2, p3};
            reinterpret_cast<float4*>(Ps + (ty * 4 + i) * 68)[tx] = pv;
#pragma unroll
            for (int j = 0; j < 4; j++) o[i][j] *= alpha;
            l_i[i] = l_i[i] * alpha;
            m_i[i] = mnew;
        }
#pragma unroll
        for (int off = 8; off >= 1; off >>= 1)
#pragma unroll
            for (int i = 0; i < 4; i++)
                rs[i] += __shfl_xor_sync(0xffffffffu, rs[i], off);
#pragma unroll
        for (int i = 0; i < 4; i++) l_i[i] += rs[i];

        __syncthreads();

        // O += P V
#pragma unroll 8
        for (int k = 0; k < 64; k++) {
            float4 vv = reinterpret_cast<const float4*>(Vs + k * 68)[tx];
#pragma unroll
            for (int i = 0; i < 4; i++) {
                float pk = Ps[(ty * 4 + i) * 68 + k];
                o[i][0] += pk * vv.x;
                o[i][1] += pk * vv.y;
                o[i][2] += pk * vv.z;
                o[i][3] += pk * vv.w;
            }
        }
    }

    const long obase = (long)b * bsO + (long)blockIdx.x * 64 * H_ + h * D_;
#pragma unroll
    for (int i = 0; i < 4; i++) {
        float inv = 1.f / l_i[i];
        float4 out = {o[i][0] * inv, o[i][1] * inv, o[i][2] * inv, o[i][3] * inv};
        reinterpret_cast<float4*>(O + obase + (long)(ty * 4 + i) * H_)[tx] = out;
    }
}

// ---------------- task-slice copies ----------------
// q1[:, :64] = q0[:, 2496:]; k1[:, :64] = k0[:, 2496:]; v1[:, :64] = q0[:, 2496:] (kv = q0 slice!)
__global__ __launch_bounds__(256) void copy_task(
    const float* __restrict__ q0, const float* __restrict__ k0,
    float* __restrict__ q1, float* __restrict__ k1, float* __restrict__ v1)
{
    int idx = blockIdx.x * blockDim.x + threadIdx.x;
    if (idx >= B_ * KL_ * H_) return;
    int b = idx / (KL_ * H_);
    int r = idx - b * (KL_ * H_);
    long src = (long)b * TOT_ * H_ + (long)MID_ * H_ + r;
    long dst = (long)b * TOT_ * H_ + r;
    float qv = q0[src];
    q1[dst] = qv;
    k1[dst] = k0[src];
    v1[dst] = qv;
}

// ---------------- launch ----------------
extern "C" void kernel_launch(void* const* d_in, const int* in_sizes, int n_in,
                              void* d_out, int out_size)
{
    const float* vis  = (const float*)d_in[0];
    const float* txt  = (const float*)d_in[1];
    const float* task = (const float*)d_in[2];
    const float* wq0  = (const float*)d_in[3];
    const float* bq0  = (const float*)d_in[4];
    const float* wk0  = (const float*)d_in[5];
    const float* bk0  = (const float*)d_in[6];
    const float* wv0  = (const float*)d_in[7];
    const float* bv0  = (const float*)d_in[8];
    const float* wq1  = (const float*)d_in[9];
    const float* bq1  = (const float*)d_in[10];
    const float* wk1  = (const float*)d_in[11];
    const float* bk1  = (const float*)d_in[12];
    const float* wv1  = (const float*)d_in[13];
    const float* bv1  = (const float*)d_in[14];
    const float* wo   = (const float*)d_in[15];
    const float* bo   = (const float*)d_in[16];
    float* out = (float*)d_out;

    float *q0, *k0, *v0, *mid, *q1, *k1, *v1, *ao;
    cudaGetSymbolAddress((void**)&q0,  g_q0);
    cudaGetSymbolAddress((void**)&k0,  g_k0);
    cudaGetSymbolAddress((void**)&v0,  g_v0);
    cudaGetSymbolAddress((void**)&mid, g_mid);
    cudaGetSymbolAddress((void**)&q1,  g_q1);
    cudaGetSymbolAddress((void**)&k1,  g_k1);
    cudaGetSymbolAddress((void**)&v1,  g_v1);
    cudaGetSymbolAddress((void**)&ao,  g_ao);

    cudaFuncSetAttribute(flash_kernel, cudaFuncAttributeMaxDynamicSharedMemorySize, FLASH_SMEM);

    const dim3 blk(256);
    const long TS = (long)TOT_ * H_;   // token-batch stride for [B,2560,...]
    const long MS = (long)MID_ * H_;   // for mid [B,2496,...]
    const float scale = 1.0f / 64.0f;

    // 1) QKV projections on the concatenated sequence (gathered)
    {
        dim3 g(H_ / 64, (B_ * TOT_) / 64, 1);
        gemm64<true><<<g, blk>>>(nullptr, 0, 0, vis, txt, task, wq0, bq0, q0, 0, H_, H_);
        gemm64<true><<<g, blk>>>(nullptr, 0, 0, vis, txt, task, wk0, bk0, k0, 0, H_, H_);
        gemm64<true><<<g, blk>>>(nullptr, 0, 0, vis, txt, task, wv0, bv0, v0, 0, H_, H_);
    }

    // 2) cross attentions -> mid
    // v2t: Q = vision queries (tok 0..2047), K/V = text (tok 2048..2495)
    flash_kernel<<<dim3(VL_ / 64, B_ * NH_), blk, FLASH_SMEM>>>(
        q0, k0 + (long)VL_ * H_, v0 + (long)VL_ * H_, mid,
        TS, TS, TS, MS, TL_, scale);
    // t2v: Q = text queries (tok 2048..2495), K/V = vision
    flash_kernel<<<dim3(TL_ / 64, B_ * NH_), blk, FLASH_SMEM>>>(
        q0 + (long)VL_ * H_, k0, v0, mid + (long)VL_ * H_,
        TS, TS, TS, MS, VL_, scale);

    // 3) per-head D x D linears on mid -> q1/k1/v1 tokens [64..2560)
    {
        dim3 g(1, (MID_ * NH_) / 64, B_);
        long midB = (long)MID_ * H_;
        gemm64<false><<<g, blk>>>(mid, D_, midB, nullptr, nullptr, nullptr,
                                  wq1, bq1, q1 + (long)KL_ * H_, TS, D_, D_);
        gemm64<false><<<g, blk>>>(mid, D_, midB, nullptr, nullptr, nullptr,
                                  wk1, bk1, k1 + (long)KL_ * H_, TS, D_, D_);
        gemm64<false><<<g, blk>>>(mid, D_, midB, nullptr, nullptr, nullptr,
                                  wv1, bv1, v1 + (long)KL_ * H_, TS, D_, D_);
    }

    // 4) task slices into tokens [0..64): q1<-kq, k1<-kk, v1<-kv(=q0 slice)
    copy_task<<<(B_ * KL_ * H_ + 255) / 256, blk>>>(q0, k0, q1, k1, v1);

    // 5) full attention over 2560 tokens
    flash_kernel<<<dim3(TOT_ / 64, B_ * NH_), blk, FLASH_SMEM>>>(
        q1, k1, v1, ao, TS, TS, TS, TS, TOT_, scale);

    // 6) output projection
    {
        dim3 g(H_ / 64, (B_ * TOT_) / 64, 1);
        gemm64<false><<<g, blk>>>(ao, H_, 0, nullptr, nullptr, nullptr,
                                  wo, bo, out, 0, H_, H_);
    }
}

// round 3
// speedup vs baseline: 1.3213x; 1.3213x over previous
#include <cuda_runtime.h>
#include <cuda_bf16.h>
#include <cstdint>

static constexpr int B_   = 2;
static constexpr int VL_  = 2048;
static constexpr int TL_  = 448;
static constexpr int KL_  = 64;
static constexpr int TOT_ = 2560;   // VL+TL+KL
static constexpr int MID_ = 2496;   // VL+TL
static constexpr int H_   = 1024;
static constexpr int NH_  = 16;
static constexpr int D_   = 64;
static constexpr int ROWS_ = B_ * TOT_;   // 5120

// ---------------- scratch (static device allocations) ----------------
__device__ float g_q0[B_*TOT_*H_];
__device__ float g_k0[B_*TOT_*H_];
__device__ float g_v0[B_*TOT_*H_];
__device__ float g_mid[B_*MID_*H_];
__device__ float g_q1[B_*TOT_*H_];
__device__ float g_k1[B_*TOT_*H_];
__device__ float g_v1[B_*TOT_*H_];
__device__ float g_ao[B_*TOT_*H_];

__device__ __nv_bfloat16 g_xh[ROWS_*H_];
__device__ __nv_bfloat16 g_xl[ROWS_*H_];
__device__ __nv_bfloat16 g_aoh[ROWS_*H_];
__device__ __nv_bfloat16 g_aol[ROWS_*H_];
__device__ __nv_bfloat16 g_wh[4][H_*H_];   // q0,k0,v0,o
__device__ __nv_bfloat16 g_wl[4][H_*H_];

// ---------------- gather helper for the 3-way concat ----------------
__device__ __forceinline__ const float* gather_row(
    const float* __restrict__ v, const float* __restrict__ t,
    const float* __restrict__ k, int r)
{
    int b   = r / TOT_;
    int tok = r - b * TOT_;
    if (tok < VL_)  return v + (size_t)(b * VL_ + tok) * H_;
    if (tok < MID_) return t + (size_t)(b * TL_ + (tok - VL_)) * H_;
    return k + (size_t)(b * KL_ + (tok - MID_)) * H_;
}

// ---------------- hi/lo bf16 split packs ----------------
__device__ __forceinline__ void split1(float x, __nv_bfloat16& h, __nv_bfloat16& l) {
    h = __float2bfloat16_rn(x);
    l = __float2bfloat16_rn(x - __bfloat162float(h));
}

__global__ __launch_bounds__(256) void pack_gather_hilo(
    const float* __restrict__ v, const float* __restrict__ t, const float* __restrict__ k,
    __nv_bfloat16* __restrict__ Xh, __nv_bfloat16* __restrict__ Xl)
{
    long i = (long)blockIdx.x * 256 + threadIdx.x;          // one float4
    if (i >= (long)ROWS_ * H_ / 4) return;
    long e = i * 4;
    int r = (int)(e / H_);
    int c = (int)(e - (long)r * H_);
    const float* row = gather_row(v, t, k, r);
    float4 x = *reinterpret_cast<const float4*>(row + c);
    __nv_bfloat16 h0,h1,h2,h3,l0,l1,l2,l3;
    split1(x.x,h0,l0); split1(x.y,h1,l1); split1(x.z,h2,l2); split1(x.w,h3,l3);
    *reinterpret_cast<__nv_bfloat162*>(Xh + e)     = __halves2bfloat162(h0, h1);
    *reinterpret_cast<__nv_bfloat162*>(Xh + e + 2) = __halves2bfloat162(h2, h3);
    *reinterpret_cast<__nv_bfloat162*>(Xl + e)     = __halves2bfloat162(l0, l1);
    *reinterpret_cast<__nv_bfloat162*>(Xl + e + 2) = __halves2bfloat162(l2, l3);
}

__global__ __launch_bounds__(256) void pack_hilo(
    const float* __restrict__ X,
    __nv_bfloat16* __restrict__ Xh, __nv_bfloat16* __restrict__ Xl, long n4)
{
    long i = (long)blockIdx.x * 256 + threadIdx.x;
    if (i >= n4) return;
    long e = i * 4;
    float4 x = *reinterpret_cast<const float4*>(X + e);
    __nv_bfloat16 h0,h1,h2,h3,l0,l1,l2,l3;
    split1(x.x,h0,l0); split1(x.y,h1,l1); split1(x.z,h2,l2); split1(x.w,h3,l3);
    *reinterpret_cast<__nv_bfloat162*>(Xh + e)     = __halves2bfloat162(h0, h1);
    *reinterpret_cast<__nv_bfloat162*>(Xh + e + 2) = __halves2bfloat162(h2, h3);
    *reinterpret_cast<__nv_bfloat162*>(Xl + e)     = __halves2bfloat162(l0, l1);
    *reinterpret_cast<__nv_bfloat162*>(Xl + e + 2) = __halves2bfloat162(l2, l3);
}

// ---------------- mma.sync helper ----------------
__device__ __forceinline__ void mma16816(
    float* c, uint32_t a0, uint32_t a1, uint32_t a2, uint32_t a3,
    uint32_t b0, uint32_t b1)
{
    asm volatile(
        "mma.sync.aligned.m16n8k16.row.col.f32.bf16.bf16.f32 "
        "{%0,%1,%2,%3}, {%4,%5,%6,%7}, {%8,%9}, {%0,%1,%2,%3};"
        : "+f"(c[0]), "+f"(c[1]), "+f"(c[2]), "+f"(c[3])
        : "r"(a0), "r"(a1), "r"(a2), "r"(a3), "r"(b0), "r"(b1));
}

// ---------------- split-bf16 HMMA GEMM ----------------
// C[M,1024] = A[M,1024] @ B[1024,1024]^T + bias; A,B pre-split hi/lo bf16.
// CTA tile 128x128, K-chunk 32, 256 threads (8 warps: 4 m x 2 n, warp tile 32x64).
static constexpr int GS   = 40;                  // smem row stride (bf16) - bank-conflict-free
static constexpr int GTE  = 128 * GS;            // elements per tile
static constexpr int GMMA_SMEM = 2 * 4 * GTE * 2; // 81920 B

__global__ __launch_bounds__(256) void gemm_mma(
    const __nv_bfloat16* __restrict__ Ah, const __nv_bfloat16* __restrict__ Al,
    const __nv_bfloat16* __restrict__ Bh, const __nv_bfloat16* __restrict__ Bl,
    const float* __restrict__ bias, float* __restrict__ C)
{
    constexpr int K = 1024;
    constexpr int NKC = K / 32;
    extern __shared__ __nv_bfloat16 sm[];
    // layout: [buf][AH, AL, BH, BL] each GTE elements
    const int tid  = threadIdx.x;
    const int wid  = tid >> 5;
    const int lane = tid & 31;
    const int wm   = wid & 3;       // 4 m-warps
    const int wn   = wid >> 2;      // 2 n-warps
    const int m0   = blockIdx.y * 128;
    const int n0   = blockIdx.x * 128;

    const __nv_bfloat16* gAh = Ah + (long)m0 * K;
    const __nv_bfloat16* gAl = Al + (long)m0 * K;
    const __nv_bfloat16* gBh = Bh + (long)n0 * K;
    const __nv_bfloat16* gBl = Bl + (long)n0 * K;

    float acc[2][8][4];
#pragma unroll
    for (int mt = 0; mt < 2; mt++)
#pragma unroll
        for (int nt = 0; nt < 8; nt++)
#pragma unroll
            for (int j = 0; j < 4; j++) acc[mt][nt][j] = 0.f;

    // ---- global -> smem loader (one k-chunk of 32) ----
    auto load_stage = [&](int buf, int kc) {
        __nv_bfloat16* s = sm + buf * 4 * GTE;
#pragma unroll
        for (int i = 0; i < 2; i++) {
            int e   = i * 256 + tid;
            int r   = e >> 2;
            int sg  = e & 3;
            long go = (long)r * K + kc * 32 + sg * 8;
            int  so = r * GS + sg * 8;
            *reinterpret_cast<uint4*>(s + so)            = *reinterpret_cast<const uint4*>(gAh + go);
            *reinterpret_cast<uint4*>(s + GTE + so)      = *reinterpret_cast<const uint4*>(gAl + go);
            *reinterpret_cast<uint4*>(s + 2 * GTE + so)  = *reinterpret_cast<const uint4*>(gBh + go);
            *reinterpret_cast<uint4*>(s + 3 * GTE + so)  = *reinterpret_cast<const uint4*>(gBl + go);
        }
    };

    const int lr = lane >> 2;          // fragment row / n index
    const int lc = (lane & 3) * 2;     // fragment k pair

    load_stage(0, 0);
    __syncthreads();

    for (int kc = 0; kc < NKC; kc++) {
        int p = kc & 1;
        if (kc + 1 < NKC) load_stage(1 - p, kc + 1);

        const __nv_bfloat16* sAH = sm + p * 4 * GTE;
        const __nv_bfloat16* sAL = sAH + GTE;
        const __nv_bfloat16* sBH = sAH + 2 * GTE;
        const __nv_bfloat16* sBL = sAH + 3 * GTE;

#pragma unroll
        for (int h = 0; h < 32; h += 16) {
            uint32_t aH[2][4], aL[2][4];
#pragma unroll
            for (int mt = 0; mt < 2; mt++) {
                int rb = (wm * 32 + mt * 16 + lr) * GS + h + lc;
                aH[mt][0] = *reinterpret_cast<const uint32_t*>(sAH + rb);
                aH[mt][1] = *reinterpret_cast<const uint32_t*>(sAH + rb + 8 * GS);
                aH[mt][2] = *reinterpret_cast<const uint32_t*>(sAH + rb + 8);
                aH[mt][3] = *reinterpret_cast<const uint32_t*>(sAH + rb + 8 * GS + 8);
                aL[mt][0] = *reinterpret_cast<const uint32_t*>(sAL + rb);
                aL[mt][1] = *reinterpret_cast<const uint32_t*>(sAL + rb + 8 * GS);
                aL[mt][2] = *reinterpret_cast<const uint32_t*>(sAL + rb + 8);
                aL[mt][3] = *reinterpret_cast<const uint32_t*>(sAL + rb + 8 * GS + 8);
            }
            uint32_t bb[8][2];
#pragma unroll
            for (int nt = 0; nt < 8; nt++) {
                int nb = (wn * 64 + nt * 8 + lr) * GS + h + lc;
                bb[nt][0] = *reinterpret_cast<const uint32_t*>(sBH + nb);
                bb[nt][1] = *reinterpret_cast<const uint32_t*>(sBH + nb + 8);
            }
#pragma unroll
            for (int mt = 0; mt < 2; mt++)
#pragma unroll
                for (int nt = 0; nt < 8; nt++)
                    mma16816(acc[mt][nt], aH[mt][0], aH[mt][1], aH[mt][2], aH[mt][3],
                             bb[nt][0], bb[nt][1]);
#pragma unroll
            for (int mt = 0; mt < 2; mt++)
#pragma unroll
                for (int nt = 0; nt < 8; nt++)
                    mma16816(acc[mt][nt], aL[mt][0], aL[mt][1], aL[mt][2], aL[mt][3],
                             bb[nt][0], bb[nt][1]);
#pragma unroll
            for (int nt = 0; nt < 8; nt++) {
                int nb = (wn * 64 + nt * 8 + lr) * GS + h + lc;
                bb[nt][0] = *reinterpret_cast<const uint32_t*>(sBL + nb);
                bb[nt][1] = *reinterpret_cast<const uint32_t*>(sBL + nb + 8);
            }
#pragma unroll
            for (int mt = 0; mt < 2; mt++)
#pragma unroll
                for (int nt = 0; nt < 8; nt++)
                    mma16816(acc[mt][nt], aH[mt][0], aH[mt][1], aH[mt][2], aH[mt][3],
                             bb[nt][0], bb[nt][1]);
        }
        __syncthreads();
    }

    // ---- epilogue ----
#pragma unroll
    for (int mt = 0; mt < 2; mt++) {
        int row0 = m0 + wm * 32 + mt * 16 + lr;
#pragma unroll
        for (int nt = 0; nt < 8; nt++) {
            int col = n0 + wn * 64 + nt * 8 + lc;
            float2 bv = *reinterpret_cast<const float2*>(bias + col);
            float2 o0 = {acc[mt][nt][0] + bv.x, acc[mt][nt][1] + bv.y};
            float2 o1 = {acc[mt][nt][2] + bv.x, acc[mt][nt][3] + bv.y};
            *reinterpret_cast<float2*>(C + (long)row0 * 1024 + col)       = o0;
            *reinterpret_cast<float2*>(C + (long)(row0 + 8) * 1024 + col) = o1;
        }
    }
}

// ---------------- fp32 GEMM (tiny per-head 64x64 linears) ----------------
template<bool GATHER>
__global__ __launch_bounds__(256) void gemm64(
    const float* __restrict__ X, int xRowStride, long xBatch,
    const float* __restrict__ Vv, const float* __restrict__ Tt, const float* __restrict__ Kk,
    const float* __restrict__ W, const float* __restrict__ bias,
    float* __restrict__ C, long cBatch, int N, int K)
{
    __shared__ float As[16][65];
    __shared__ float Bs[16][65];
    __shared__ const float* rowp[64];

    const int tid = threadIdx.x;
    const int ty  = tid >> 4;
    const int tx  = tid & 15;
    const int m0  = blockIdx.y * 64;
    const int n0  = blockIdx.x * 64;
    const int bz  = blockIdx.z;

    if (tid < 64) {
        int m = m0 + tid;
        if (GATHER) rowp[tid] = gather_row(Vv, Tt, Kk, m);
        else        rowp[tid] = X + (long)bz * xBatch + (long)m * xRowStride;
    }
    __syncthreads();

    const int c  = tid & 15;
    const int r0 = tid >> 4;

    const float* xr[4];
    const float* wr[4];
#pragma unroll
    for (int i = 0; i < 4; i++) {
        xr[i] = rowp[r0 + i * 16];
        wr[i] = W + (long)(n0 + r0 + i * 16) * K;
    }

    float acc[4][4];
#pragma unroll
    for (int i = 0; i < 4; i++)
#pragma unroll
        for (int j = 0; j < 4; j++) acc[i][j] = 0.f;

    for (int k0 = 0; k0 < K; k0 += 16) {
#pragma unroll
        for (int i = 0; i < 4; i++) {
            As[c][r0 + i * 16] = xr[i][k0 + c];
            Bs[c][r0 + i * 16] = wr[i][k0 + c];
        }
        __syncthreads();
#pragma unroll
        for (int kk = 0; kk < 16; kk++) {
            float a[4], b[4];
#pragma unroll
            for (int i = 0; i < 4; i++) a[i] = As[kk][ty * 4 + i];
#pragma unroll
            for (int j = 0; j < 4; j++) b[j] = Bs[kk][tx * 4 + j];
#pragma unroll
            for (int i = 0; i < 4; i++)
#pragma unroll
                for (int j = 0; j < 4; j++) acc[i][j] += a[i] * b[j];
        }
        __syncthreads();
    }

    float bb[4];
#pragma unroll
    for (int j = 0; j < 4; j++) bb[j] = bias[n0 + tx * 4 + j];

#pragma unroll
    for (int i = 0; i < 4; i++) {
        float4 out;
        out.x = acc[i][0] + bb[0];
        out.y = acc[i][1] + bb[1];
        out.z = acc[i][2] + bb[2];
        out.w = acc[i][3] + bb[3];
        long off = (long)bz * cBatch + (long)(m0 + ty * 4 + i) * N + n0 + tx * 4;
        *reinterpret_cast<float4*>(C + off) = out;
    }
}

// ---------------- Flash attention (unchanged) ----------------
static constexpr int FLASH_SMEM = 4 * 64 * 68 * (int)sizeof(float);

__global__ __launch_bounds__(256) void flash_kernel(
    const float* __restrict__ Q, const float* __restrict__ K,
    const float* __restrict__ V, float* __restrict__ O,
    long bsQ, long bsK, long bsV, long bsO,
    int klen, float scale)
{
    extern __shared__ float smf[];
    float* Qs = smf;
    float* Ks = smf + 64 * 68;
    float* Vs = smf + 2 * 64 * 68;
    float* Ps = smf + 3 * 64 * 68;

    const int tid = threadIdx.x;
    const int ty  = tid >> 4;
    const int tx  = tid & 15;
    const int b   = blockIdx.y >> 4;
    const int h   = blockIdx.y & 15;

    const long qbase = (long)b * bsQ + (long)blockIdx.x * 64 * H_ + h * D_;
#pragma unroll
    for (int i = 0; i < 4; i++) {
        int idx = tid + i * 256;
        int r = idx >> 4, c4 = idx & 15;
        float4 v = *reinterpret_cast<const float4*>(Q + qbase + (long)r * H_ + c4 * 4);
        reinterpret_cast<float4*>(Qs + r * 68)[c4] = v;
    }

    float m_i[4], l_i[4], o[4][4];
#pragma unroll
    for (int i = 0; i < 4; i++) {
        m_i[i] = -1e30f;
        l_i[i] = 0.f;
#pragma unroll
        for (int j = 0; j < 4; j++) o[i][j] = 0.f;
    }

    const long kbase = (long)b * bsK + h * D_;
    const long vbase = (long)b * bsV + h * D_;
    const int ntiles = klen >> 6;

    for (int kt = 0; kt < ntiles; kt++) {
        __syncthreads();
#pragma unroll
        for (int i = 0; i < 4; i++) {
            int idx = tid + i * 256;
            int r = idx >> 4, c4 = idx & 15;
            long toff = (long)(kt * 64 + r) * H_ + c4 * 4;
            reinterpret_cast<float4*>(Ks + r * 68)[c4] =
                *reinterpret_cast<const float4*>(K + kbase + toff);
            reinterpret_cast<float4*>(Vs + r * 68)[c4] =
                *reinterpret_cast<const float4*>(V + vbase + toff);
        }
        __syncthreads();

        float s[4][4];
#pragma unroll
        for (int i = 0; i < 4; i++)
#pragma unroll
            for (int j = 0; j < 4; j++) s[i][j] = 0.f;

#pragma unroll 8
        for (int d = 0; d < 64; d++) {
            float a[4], bb[4];
#pragma unroll
            for (int i = 0; i < 4; i++) a[i]  = Qs[(ty * 4 + i) * 68 + d];
#pragma unroll
            for (int j = 0; j < 4; j++) bb[j] = Ks[(tx * 4 + j) * 68 + d];
#pragma unroll
            for (int i = 0; i < 4; i++)
#pragma unroll
                for (int j = 0; j < 4; j++) s[i][j] += a[i] * bb[j];
        }

        float rm[4];
#pragma unroll
        for (int i = 0; i < 4; i++) {
#pragma unroll
            for (int j = 0; j < 4; j++) s[i][j] *= scale;
            rm[i] = fmaxf(fmaxf(s[i][0], s[i][1]), fmaxf(s[i][2], s[i][3]));
        }
#pragma unroll
        for (int off = 8; off >= 1; off >>= 1)
#pragma unroll
            for (int i = 0; i < 4; i++)
                rm[i] = fmaxf(rm[i], __shfl_xor_sync(0xffffffffu, rm[i], off));

        float rs[4];
#pragma unroll
        for (int i = 0; i < 4; i++) {
            float mnew  = fmaxf(m_i[i], rm[i]);
            float alpha = __expf(m_i[i] - mnew);
            float p0 = __expf(s[i][0] - mnew);
            float p1 = __expf(s[i][1] - mnew);
            float p2 = __expf(s[i][2] - mnew);
            float p3 = __expf(s[i][3] - mnew);
            rs[i] = p0 + p1 + p2 + p3;
            float4 pv = {p0, p1, p2, p3};
            reinterpret_cast<float4*>(Ps + (ty * 4 + i) * 68)[tx] = pv;
#pragma unroll
            for (int j = 0; j < 4; j++) o[i][j] *= alpha;
            l_i[i] = l_i[i] * alpha;
            m_i[i] = mnew;
        }
#pragma unroll
        for (int off = 8; off >= 1; off >>= 1)
#pragma unroll
            for (int i = 0; i < 4; i++)
                rs[i] += __shfl_xor_sync(0xffffffffu, rs[i], off);
#pragma unroll
        for (int i = 0; i < 4; i++) l_i[i] += rs[i];

        __syncthreads();

#pragma unroll 8
        for (int k = 0; k < 64; k++) {
            float4 vv = reinterpret_cast<const float4*>(Vs + k * 68)[tx];
#pragma unroll
            for (int i = 0; i < 4; i++) {
                float pk = Ps[(ty * 4 + i) * 68 + k];
                o[i][0] += pk * vv.x;
                o[i][1] += pk * vv.y;
                o[i][2] += pk * vv.z;
                o[i][3] += pk * vv.w;
            }
        }
    }

    const long obase = (long)b * bsO + (long)blockIdx.x * 64 * H_ + h * D_;
#pragma unroll
    for (int i = 0; i < 4; i++) {
        float inv = 1.f / l_i[i];
        float4 out = {o[i][0] * inv, o[i][1] * inv, o[i][2] * inv, o[i][3] * inv};
        reinterpret_cast<float4*>(O + obase + (long)(ty * 4 + i) * H_)[tx] = out;
    }
}

// ---------------- task-slice copies ----------------
__global__ __launch_bounds__(256) void copy_task(
    const float* __restrict__ q0, const float* __restrict__ k0,
    float* __restrict__ q1, float* __restrict__ k1, float* __restrict__ v1)
{
    int idx = blockIdx.x * blockDim.x + threadIdx.x;
    if (idx >= B_ * KL_ * H_) return;
    int b = idx / (KL_ * H_);
    int r = idx - b * (KL_ * H_);
    long src = (long)b * TOT_ * H_ + (long)MID_ * H_ + r;
    long dst = (long)b * TOT_ * H_ + r;
    float qv = q0[src];
    q1[dst] = qv;
    k1[dst] = k0[src];
    v1[dst] = qv;
}

// ---------------- launch ----------------
extern "C" void kernel_launch(void* const* d_in, const int* in_sizes, int n_in,
                              void* d_out, int out_size)
{
    const float* vis  = (const float*)d_in[0];
    const float* txt  = (const float*)d_in[1];
    const float* task = (const float*)d_in[2];
    const float* wq0  = (const float*)d_in[3];
    const float* bq0  = (const float*)d_in[4];
    const float* wk0  = (const float*)d_in[5];
    const float* bk0  = (const float*)d_in[6];
    const float* wv0  = (const float*)d_in[7];
    const float* bv0  = (const float*)d_in[8];
    const float* wq1  = (const float*)d_in[9];
    const float* bq1  = (const float*)d_in[10];
    const float* wk1  = (const float*)d_in[11];
    const float* bk1  = (const float*)d_in[12];
    const float* wv1  = (const float*)d_in[13];
    const float* bv1  = (const float*)d_in[14];
    const float* wo   = (const float*)d_in[15];
    const float* bo   = (const float*)d_in[16];
    float* out = (float*)d_out;

    float *q0, *k0, *v0, *mid, *q1, *k1, *v1, *ao;
    cudaGetSymbolAddress((void**)&q0,  g_q0);
    cudaGetSymbolAddress((void**)&k0,  g_k0);
    cudaGetSymbolAddress((void**)&v0,  g_v0);
    cudaGetSymbolAddress((void**)&mid, g_mid);
    cudaGetSymbolAddress((void**)&q1,  g_q1);
    cudaGetSymbolAddress((void**)&k1,  g_k1);
    cudaGetSymbolAddress((void**)&v1,  g_v1);
    cudaGetSymbolAddress((void**)&ao,  g_ao);

    __nv_bfloat16 *xh, *xl, *aoh, *aol, *wh, *wl;
    cudaGetSymbolAddress((void**)&xh,  g_xh);
    cudaGetSymbolAddress((void**)&xl,  g_xl);
    cudaGetSymbolAddress((void**)&aoh, g_aoh);
    cudaGetSymbolAddress((void**)&aol, g_aol);
    cudaGetSymbolAddress((void**)&wh,  g_wh);
    cudaGetSymbolAddress((void**)&wl,  g_wl);

    cudaFuncSetAttribute(flash_kernel, cudaFuncAttributeMaxDynamicSharedMemorySize, FLASH_SMEM);
    cudaFuncSetAttribute(gemm_mma, cudaFuncAttributeMaxDynamicSharedMemorySize, GMMA_SMEM);

    const dim3 blk(256);
    const long TS = (long)TOT_ * H_;
    const long MS = (long)MID_ * H_;
    const float scale = 1.0f / 64.0f;
    const long WN4 = (long)H_ * H_ / 4;

    // 0) pack inputs to hi/lo bf16
    pack_gather_hilo<<<ROWS_ * H_ / 1024, blk>>>(vis, txt, task, xh, xl);
    pack_hilo<<<(int)(WN4 / 256), blk>>>(wq0, wh + 0L * H_ * H_, wl + 0L * H_ * H_, WN4);
    pack_hilo<<<(int)(WN4 / 256), blk>>>(wk0, wh + 1L * H_ * H_, wl + 1L * H_ * H_, WN4);
    pack_hilo<<<(int)(WN4 / 256), blk>>>(wv0, wh + 2L * H_ * H_, wl + 2L * H_ * H_, WN4);
    pack_hilo<<<(int)(WN4 / 256), blk>>>(wo,  wh + 3L * H_ * H_, wl + 3L * H_ * H_, WN4);

    // 1) QKV projections via split-bf16 HMMA GEMM
    {
        dim3 g(H_ / 128, ROWS_ / 128);
        gemm_mma<<<g, blk, GMMA_SMEM>>>(xh, xl, wh + 0L*H_*H_, wl + 0L*H_*H_, bq0, q0);
        gemm_mma<<<g, blk, GMMA_SMEM>>>(xh, xl, wh + 1L*H_*H_, wl + 1L*H_*H_, bk0, k0);
        gemm_mma<<<g, blk, GMMA_SMEM>>>(xh, xl, wh + 2L*H_*H_, wl + 2L*H_*H_, bv0, v0);
    }

    // 2) cross attentions -> mid
    flash_kernel<<<dim3(VL_ / 64, B_ * NH_), blk, FLASH_SMEM>>>(
        q0, k0 + (long)VL_ * H_, v0 + (long)VL_ * H_, mid,
        TS, TS, TS, MS, TL_, scale);
    flash_kernel<<<dim3(TL_ / 64, B_ * NH_), blk, FLASH_SMEM>>>(
        q0 + (long)VL_ * H_, k0, v0, mid + (long)VL_ * H_,
        TS, TS, TS, MS, VL_, scale);

    // 3) per-head D x D linears on mid -> q1/k1/v1 tokens [64..2560)
    {
        dim3 g(1, (MID_ * NH_) / 64, B_);
        long midB = (long)MID_ * H_;
        gemm64<false><<<g, blk>>>(mid, D_, midB, nullptr, nullptr, nullptr,
                                  wq1, bq1, q1 + (long)KL_ * H_, TS, D_, D_);
        gemm64<false><<<g, blk>>>(mid, D_, midB, nullptr, nullptr, nullptr,
                                  wk1, bk1, k1 + (long)KL_ * H_, TS, D_, D_);
        gemm64<false><<<g, blk>>>(mid, D_, midB, nullptr, nullptr, nullptr,
                                  wv1, bv1, v1 + (long)KL_ * H_, TS, D_, D_);
    }

    // 4) task slices
    copy_task<<<(B_ * KL_ * H_ + 255) / 256, blk>>>(q0, k0, q1, k1, v1);

    // 5) full attention
    flash_kernel<<<dim3(TOT_ / 64, B_ * NH_), blk, FLASH_SMEM>>>(
        q1, k1, v1, ao, TS, TS, TS, TS, TOT_, scale);

    // 6) output projection via HMMA
    pack_hilo<<<ROWS_ * H_ / 1024, blk>>>(ao, aoh, aol, (long)ROWS_ * H_ / 4);
    {
        dim3 g(H_ / 128, ROWS_ / 128);
        gemm_mma<<<g, blk, GMMA_SMEM>>>(aoh, aol, wh + 3L*H_*H_, wl + 3L*H_*H_, bo, out);
    }
}

// round 4
// speedup vs baseline: 3.6451x; 2.7588x over previous
#include <cuda_runtime.h>
#include <cuda_bf16.h>
#include <cstdint>

static constexpr int B_   = 2;
static constexpr int VL_  = 2048;
static constexpr int TL_  = 448;
static constexpr int KL_  = 64;
static constexpr int TOT_ = 2560;   // VL+TL+KL
static constexpr int MID_ = 2496;   // VL+TL
static constexpr int H_   = 1024;
static constexpr int NH_  = 16;
static constexpr int D_   = 64;
static constexpr int ROWS_ = B_ * TOT_;   // 5120

// ---------------- scratch (static device allocations) ----------------
__device__ float g_q0[B_*TOT_*H_];
__device__ float g_k0[B_*TOT_*H_];
__device__ float g_v0[B_*TOT_*H_];
__device__ float g_mid[B_*MID_*H_];
__device__ float g_q1[B_*TOT_*H_];
__device__ float g_k1[B_*TOT_*H_];
__device__ float g_v1[B_*TOT_*H_];
__device__ float g_ao[B_*TOT_*H_];

__device__ __nv_bfloat16 g_xh[ROWS_*H_];
__device__ __nv_bfloat16 g_xl[ROWS_*H_];
__device__ __nv_bfloat16 g_aoh[ROWS_*H_];
__device__ __nv_bfloat16 g_aol[ROWS_*H_];
__device__ __nv_bfloat16 g_wh[4][H_*H_];   // q0,k0,v0,o
__device__ __nv_bfloat16 g_wl[4][H_*H_];

// ---------------- gather helper for the 3-way concat ----------------
__device__ __forceinline__ const float* gather_row(
    const float* __restrict__ v, const float* __restrict__ t,
    const float* __restrict__ k, int r)
{
    int b   = r / TOT_;
    int tok = r - b * TOT_;
    if (tok < VL_)  return v + (size_t)(b * VL_ + tok) * H_;
    if (tok < MID_) return t + (size_t)(b * TL_ + (tok - VL_)) * H_;
    return k + (size_t)(b * KL_ + (tok - MID_)) * H_;
}

// ---------------- hi/lo bf16 split helpers ----------------
__device__ __forceinline__ void split1(float x, __nv_bfloat16& h, __nv_bfloat16& l) {
    h = __float2bfloat16_rn(x);
    l = __float2bfloat16_rn(x - __bfloat162float(h));
}

__device__ __forceinline__ void split_store4(
    float4 x, __nv_bfloat16* ph, __nv_bfloat16* pl)
{
    __nv_bfloat16 h0,h1,h2,h3,l0,l1,l2,l3;
    split1(x.x,h0,l0); split1(x.y,h1,l1); split1(x.z,h2,l2); split1(x.w,h3,l3);
    *reinterpret_cast<__nv_bfloat162*>(ph)     = __halves2bfloat162(h0, h1);
    *reinterpret_cast<__nv_bfloat162*>(ph + 2) = __halves2bfloat162(h2, h3);
    *reinterpret_cast<__nv_bfloat162*>(pl)     = __halves2bfloat162(l0, l1);
    *reinterpret_cast<__nv_bfloat162*>(pl + 2) = __halves2bfloat162(l2, l3);
}

__device__ __forceinline__ void pack_hl(float x, float y, uint32_t& hi, uint32_t& lo) {
    __nv_bfloat162 h = __floats2bfloat162_rn(x, y);
    float hx = __bfloat162float(h.x), hy = __bfloat162float(h.y);
    __nv_bfloat162 l = __floats2bfloat162_rn(x - hx, y - hy);
    hi = *reinterpret_cast<uint32_t*>(&h);
    lo = *reinterpret_cast<uint32_t*>(&l);
}

__global__ __launch_bounds__(256) void pack_gather_hilo(
    const float* __restrict__ v, const float* __restrict__ t, const float* __restrict__ k,
    __nv_bfloat16* __restrict__ Xh, __nv_bfloat16* __restrict__ Xl)
{
    long i = (long)blockIdx.x * 256 + threadIdx.x;
    if (i >= (long)ROWS_ * H_ / 4) return;
    long e = i * 4;
    int r = (int)(e / H_);
    int c = (int)(e - (long)r * H_);
    const float* row = gather_row(v, t, k, r);
    float4 x = *reinterpret_cast<const float4*>(row + c);
    split_store4(x, Xh + e, Xl + e);
}

__global__ __launch_bounds__(256) void pack_hilo(
    const float* __restrict__ X,
    __nv_bfloat16* __restrict__ Xh, __nv_bfloat16* __restrict__ Xl, long n4)
{
    long i = (long)blockIdx.x * 256 + threadIdx.x;
    if (i >= n4) return;
    long e = i * 4;
    float4 x = *reinterpret_cast<const float4*>(X + e);
    split_store4(x, Xh + e, Xl + e);
}

// ---------------- mma.sync / ldmatrix helpers ----------------
__device__ __forceinline__ void mma16816(
    float* c, uint32_t a0, uint32_t a1, uint32_t a2, uint32_t a3,
    uint32_t b0, uint32_t b1)
{
    asm volatile(
        "mma.sync.aligned.m16n8k16.row.col.f32.bf16.bf16.f32 "
        "{%0,%1,%2,%3}, {%4,%5,%6,%7}, {%8,%9}, {%0,%1,%2,%3};"
        : "+f"(c[0]), "+f"(c[1]), "+f"(c[2]), "+f"(c[3])
        : "r"(a0), "r"(a1), "r"(a2), "r"(a3), "r"(b0), "r"(b1));
}

__device__ __forceinline__ void ldmx4t(
    uint32_t& r0, uint32_t& r1, uint32_t& r2, uint32_t& r3, uint32_t addr)
{
    asm volatile(
        "ldmatrix.sync.aligned.m8n8.x4.trans.shared.b16 {%0,%1,%2,%3}, [%4];"
        : "=r"(r0), "=r"(r1), "=r"(r2), "=r"(r3) : "r"(addr));
}

__device__ __forceinline__ uint32_t smem_u32(const void* p) {
    uint32_t a;
    asm("{ .reg .u64 t; cvta.to.shared.u64 t, %1; cvt.u32.u64 %0, t; }" : "=r"(a) : "l"(p));
    return a;
}

// ---------------- split-bf16 HMMA GEMM (unchanged from R3) ----------------
static constexpr int GS   = 40;
static constexpr int GTE  = 128 * GS;
static constexpr int GMMA_SMEM = 2 * 4 * GTE * 2;

__global__ __launch_bounds__(256) void gemm_mma(
    const __nv_bfloat16* __restrict__ Ah, const __nv_bfloat16* __restrict__ Al,
    const __nv_bfloat16* __restrict__ Bh, const __nv_bfloat16* __restrict__ Bl,
    const float* __restrict__ bias, float* __restrict__ C)
{
    constexpr int K = 1024;
    constexpr int NKC = K / 32;
    extern __shared__ __nv_bfloat16 sm[];
    const int tid  = threadIdx.x;
    const int wid  = tid >> 5;
    const int lane = tid & 31;
    const int wm   = wid & 3;
    const int wn   = wid >> 2;
    const int m0   = blockIdx.y * 128;
    const int n0   = blockIdx.x * 128;

    const __nv_bfloat16* gAh = Ah + (long)m0 * K;
    const __nv_bfloat16* gAl = Al + (long)m0 * K;
    const __nv_bfloat16* gBh = Bh + (long)n0 * K;
    const __nv_bfloat16* gBl = Bl + (long)n0 * K;

    float acc[2][8][4];
#pragma unroll
    for (int mt = 0; mt < 2; mt++)
#pragma unroll
        for (int nt = 0; nt < 8; nt++)
#pragma unroll
            for (int j = 0; j < 4; j++) acc[mt][nt][j] = 0.f;

    auto load_stage = [&](int buf, int kc) {
        __nv_bfloat16* s = sm + buf * 4 * GTE;
#pragma unroll
        for (int i = 0; i < 2; i++) {
            int e   = i * 256 + tid;
            int r   = e >> 2;
            int sg  = e & 3;
            long go = (long)r * K + kc * 32 + sg * 8;
            int  so = r * GS + sg * 8;
            *reinterpret_cast<uint4*>(s + so)            = *reinterpret_cast<const uint4*>(gAh + go);
            *reinterpret_cast<uint4*>(s + GTE + so)      = *reinterpret_cast<const uint4*>(gAl + go);
            *reinterpret_cast<uint4*>(s + 2 * GTE + so)  = *reinterpret_cast<const uint4*>(gBh + go);
            *reinterpret_cast<uint4*>(s + 3 * GTE + so)  = *reinterpret_cast<const uint4*>(gBl + go);
        }
    };

    const int lr = lane >> 2;
    const int lc = (lane & 3) * 2;

    load_stage(0, 0);
    __syncthreads();

    for (int kc = 0; kc < NKC; kc++) {
        int p = kc & 1;
        if (kc + 1 < NKC) load_stage(1 - p, kc + 1);

        const __nv_bfloat16* sAH = sm + p * 4 * GTE;
        const __nv_bfloat16* sAL = sAH + GTE;
        const __nv_bfloat16* sBH = sAH + 2 * GTE;
        const __nv_bfloat16* sBL = sAH + 3 * GTE;

#pragma unroll
        for (int h = 0; h < 32; h += 16) {
            uint32_t aH[2][4], aL[2][4];
#pragma unroll
            for (int mt = 0; mt < 2; mt++) {
                int rb = (wm * 32 + mt * 16 + lr) * GS + h + lc;
                aH[mt][0] = *reinterpret_cast<const uint32_t*>(sAH + rb);
                aH[mt][1] = *reinterpret_cast<const uint32_t*>(sAH + rb + 8 * GS);
                aH[mt][2] = *reinterpret_cast<const uint32_t*>(sAH + rb + 8);
                aH[mt][3] = *reinterpret_cast<const uint32_t*>(sAH + rb + 8 * GS + 8);
                aL[mt][0] = *reinterpret_cast<const uint32_t*>(sAL + rb);
                aL[mt][1] = *reinterpret_cast<const uint32_t*>(sAL + rb + 8 * GS);
                aL[mt][2] = *reinterpret_cast<const uint32_t*>(sAL + rb + 8);
                aL[mt][3] = *reinterpret_cast<const uint32_t*>(sAL + rb + 8 * GS + 8);
            }
            uint32_t bb[8][2];
#pragma unroll
            for (int nt = 0; nt < 8; nt++) {
                int nb = (wn * 64 + nt * 8 + lr) * GS + h + lc;
                bb[nt][0] = *reinterpret_cast<const uint32_t*>(sBH + nb);
                bb[nt][1] = *reinterpret_cast<const uint32_t*>(sBH + nb + 8);
            }
#pragma unroll
            for (int mt = 0; mt < 2; mt++)
#pragma unroll
                for (int nt = 0; nt < 8; nt++)
                    mma16816(acc[mt][nt], aH[mt][0], aH[mt][1], aH[mt][2], aH[mt][3],
                             bb[nt][0], bb[nt][1]);
#pragma unroll
            for (int mt = 0; mt < 2; mt++)
#pragma unroll
                for (int nt = 0; nt < 8; nt++)
                    mma16816(acc[mt][nt], aL[mt][0], aL[mt][1], aL[mt][2], aL[mt][3],
                             bb[nt][0], bb[nt][1]);
#pragma unroll
            for (int nt = 0; nt < 8; nt++) {
                int nb = (wn * 64 + nt * 8 + lr) * GS + h + lc;
                bb[nt][0] = *reinterpret_cast<const uint32_t*>(sBL + nb);
                bb[nt][1] = *reinterpret_cast<const uint32_t*>(sBL + nb + 8);
            }
#pragma unroll
            for (int mt = 0; mt < 2; mt++)
#pragma unroll
                for (int nt = 0; nt < 8; nt++)
                    mma16816(acc[mt][nt], aH[mt][0], aH[mt][1], aH[mt][2], aH[mt][3],
                             bb[nt][0], bb[nt][1]);
        }
        __syncthreads();
    }

#pragma unroll
    for (int mt = 0; mt < 2; mt++) {
        int row0 = m0 + wm * 32 + mt * 16 + lr;
#pragma unroll
        for (int nt = 0; nt < 8; nt++) {
            int col = n0 + wn * 64 + nt * 8 + lc;
            float2 bv = *reinterpret_cast<const float2*>(bias + col);
            float2 o0 = {acc[mt][nt][0] + bv.x, acc[mt][nt][1] + bv.y};
            float2 o1 = {acc[mt][nt][2] + bv.x, acc[mt][nt][3] + bv.y};
            *reinterpret_cast<float2*>(C + (long)row0 * 1024 + col)       = o0;
            *reinterpret_cast<float2*>(C + (long)(row0 + 8) * 1024 + col) = o1;
        }
    }
}

// ---------------- fp32 GEMM (tiny per-head 64x64 linears) ----------------
template<bool GATHER>
__global__ __launch_bounds__(256) void gemm64(
    const float* __restrict__ X, int xRowStride, long xBatch,
    const float* __restrict__ Vv, const float* __restrict__ Tt, const float* __restrict__ Kk,
    const float* __restrict__ W, const float* __restrict__ bias,
    float* __restrict__ C, long cBatch, int N, int K)
{
    __shared__ float As[16][65];
    __shared__ float Bs[16][65];
    __shared__ const float* rowp[64];

    const int tid = threadIdx.x;
    const int ty  = tid >> 4;
    const int tx  = tid & 15;
    const int m0  = blockIdx.y * 64;
    const int n0  = blockIdx.x * 64;
    const int bz  = blockIdx.z;

    if (tid < 64) {
        int m = m0 + tid;
        if (GATHER) rowp[tid] = gather_row(Vv, Tt, Kk, m);
        else        rowp[tid] = X + (long)bz * xBatch + (long)m * xRowStride;
    }
    __syncthreads();

    const int c  = tid & 15;
    const int r0 = tid >> 4;

    const float* xr[4];
    const float* wr[4];
#pragma unroll
    for (int i = 0; i < 4; i++) {
        xr[i] = rowp[r0 + i * 16];
        wr[i] = W + (long)(n0 + r0 + i * 16) * K;
    }

    float acc[4][4];
#pragma unroll
    for (int i = 0; i < 4; i++)
#pragma unroll
        for (int j = 0; j < 4; j++) acc[i][j] = 0.f;

    for (int k0 = 0; k0 < K; k0 += 16) {
#pragma unroll
        for (int i = 0; i < 4; i++) {
            As[c][r0 + i * 16] = xr[i][k0 + c];
            Bs[c][r0 + i * 16] = wr[i][k0 + c];
        }
        __syncthreads();
#pragma unroll
        for (int kk = 0; kk < 16; kk++) {
            float a[4], b[4];
#pragma unroll
            for (int i = 0; i < 4; i++) a[i] = As[kk][ty * 4 + i];
#pragma unroll
            for (int j = 0; j < 4; j++) b[j] = Bs[kk][tx * 4 + j];
#pragma unroll
            for (int i = 0; i < 4; i++)
#pragma unroll
                for (int j = 0; j < 4; j++) acc[i][j] += a[i] * b[j];
        }
        __syncthreads();
    }

    float bb[4];
#pragma unroll
    for (int j = 0; j < 4; j++) bb[j] = bias[n0 + tx * 4 + j];

#pragma unroll
    for (int i = 0; i < 4; i++) {
        float4 out;
        out.x = acc[i][0] + bb[0];
        out.y = acc[i][1] + bb[1];
        out.z = acc[i][2] + bb[2];
        out.w = acc[i][3] + bb[3];
        long off = (long)bz * cBatch + (long)(m0 + ty * 4 + i) * N + n0 + tx * 4;
        *reinterpret_cast<float4*>(C + off) = out;
    }
}

// ---------------- Flash attention on tensor cores ----------------
// 64 queries per block, 4 warps (16 rows each), D=64, key tiles of 64.
// Q/K split hi/lo in smem (stride 72); V row-major hi/lo, B-frags via ldmatrix.trans.
static constexpr int FS = 72;
static constexpr int FLASH2_SMEM = 6 * 64 * FS * 2;   // 55296 B

__global__ __launch_bounds__(128) void flash_mma(
    const float* __restrict__ Q, const float* __restrict__ K,
    const float* __restrict__ V, float* __restrict__ O,
    long bsQ, long bsK, long bsV, long bsO,
    int klen, float scale)
{
    extern __shared__ __nv_bfloat16 sb[];
    __nv_bfloat16* Qh = sb;
    __nv_bfloat16* Ql = sb + 64 * FS;
    __nv_bfloat16* Kh = sb + 2 * 64 * FS;
    __nv_bfloat16* Kl = sb + 3 * 64 * FS;
    __nv_bfloat16* Vh = sb + 4 * 64 * FS;
    __nv_bfloat16* Vl = sb + 5 * 64 * FS;

    const int tid  = threadIdx.x;
    const int wid  = tid >> 5;
    const int lane = tid & 31;
    const int lr   = lane >> 2;
    const int lc   = (lane & 3) * 2;
    const int b    = blockIdx.y >> 4;
    const int h    = blockIdx.y & 15;

    const uint32_t uVh = smem_u32(Vh);
    const uint32_t uVl = smem_u32(Vl);

    // load + split Q tile [64 x 64]
    const long qbase = (long)b * bsQ + (long)blockIdx.x * 64 * H_ + h * D_;
#pragma unroll
    for (int i = 0; i < 8; i++) {
        int e = i * 128 + tid;
        int r = e >> 4, c = (e & 15) * 4;
        float4 x = *reinterpret_cast<const float4*>(Q + qbase + (long)r * H_ + c);
        split_store4(x, Qh + r * FS + c, Ql + r * FS + c);
    }

    float m0 = -1e30f, m1 = -1e30f, li0 = 0.f, li1 = 0.f;
    float o[8][4];
#pragma unroll
    for (int nt = 0; nt < 8; nt++)
#pragma unroll
        for (int j = 0; j < 4; j++) o[nt][j] = 0.f;

    const long kb = (long)b * bsK + h * D_;
    const long vb = (long)b * bsV + h * D_;
    const int ntiles = klen >> 6;

    for (int kt = 0; kt < ntiles; kt++) {
        __syncthreads();
#pragma unroll
        for (int i = 0; i < 8; i++) {
            int e = i * 128 + tid;
            int r = e >> 4, c = (e & 15) * 4;
            long go = (long)(kt * 64 + r) * H_ + c;
            float4 xk = *reinterpret_cast<const float4*>(K + kb + go);
            split_store4(xk, Kh + r * FS + c, Kl + r * FS + c);
            float4 xv = *reinterpret_cast<const float4*>(V + vb + go);
            split_store4(xv, Vh + r * FS + c, Vl + r * FS + c);
        }
        __syncthreads();

        // ---- S = Q K^T (split: QhKh + QhKl + QlKh) ----
        float s[8][4];
#pragma unroll
        for (int nt = 0; nt < 8; nt++)
#pragma unroll
            for (int j = 0; j < 4; j++) s[nt][j] = 0.f;

#pragma unroll
        for (int ks = 0; ks < 4; ks++) {
            int ab = (wid * 16 + lr) * FS + ks * 16 + lc;
            uint32_t aH0 = *reinterpret_cast<const uint32_t*>(Qh + ab);
            uint32_t aH1 = *reinterpret_cast<const uint32_t*>(Qh + ab + 8 * FS);
            uint32_t aH2 = *reinterpret_cast<const uint32_t*>(Qh + ab + 8);
            uint32_t aH3 = *reinterpret_cast<const uint32_t*>(Qh + ab + 8 * FS + 8);
            uint32_t aL0 = *reinterpret_cast<const uint32_t*>(Ql + ab);
            uint32_t aL1 = *reinterpret_cast<const uint32_t*>(Ql + ab + 8 * FS);
            uint32_t aL2 = *reinterpret_cast<const uint32_t*>(Ql + ab + 8);
            uint32_t aL3 = *reinterpret_cast<const uint32_t*>(Ql + ab + 8 * FS + 8);
#pragma unroll
            for (int nt = 0; nt < 8; nt++) {
                int nb = (nt * 8 + lr) * FS + ks * 16 + lc;
                uint32_t bh0 = *reinterpret_cast<const uint32_t*>(Kh + nb);
                uint32_t bh1 = *reinterpret_cast<const uint32_t*>(Kh + nb + 8);
                uint32_t bl0 = *reinterpret_cast<const uint32_t*>(Kl + nb);
                uint32_t bl1 = *reinterpret_cast<const uint32_t*>(Kl + nb + 8);
                mma16816(s[nt], aH0, aH1, aH2, aH3, bh0, bh1);
                mma16816(s[nt], aH0, aH1, aH2, aH3, bl0, bl1);
                mma16816(s[nt], aL0, aL1, aL2, aL3, bh0, bh1);
            }
        }

        // ---- online softmax (rows lr and lr+8 of this warp's 16) ----
        float rm0 = -1e30f, rm1 = -1e30f;
#pragma unroll
        for (int nt = 0; nt < 8; nt++) {
            rm0 = fmaxf(rm0, fmaxf(s[nt][0], s[nt][1]));
            rm1 = fmaxf(rm1, fmaxf(s[nt][2], s[nt][3]));
        }
        rm0 *= scale; rm1 *= scale;
#pragma unroll
        for (int off = 1; off <= 2; off <<= 1) {
            rm0 = fmaxf(rm0, __shfl_xor_sync(0xffffffffu, rm0, off));
            rm1 = fmaxf(rm1, __shfl_xor_sync(0xffffffffu, rm1, off));
        }
        float mn0 = fmaxf(m0, rm0), mn1 = fmaxf(m1, rm1);
        float al0 = __expf(m0 - mn0), al1 = __expf(m1 - mn1);

        float rs0 = 0.f, rs1 = 0.f;
#pragma unroll
        for (int nt = 0; nt < 8; nt++) {
            float p0 = __expf(fmaf(s[nt][0], scale, -mn0));
            float p1 = __expf(fmaf(s[nt][1], scale, -mn0));
            float p2 = __expf(fmaf(s[nt][2], scale, -mn1));
            float p3 = __expf(fmaf(s[nt][3], scale, -mn1));
            rs0 += p0 + p1; rs1 += p2 + p3;
            s[nt][0] = p0; s[nt][1] = p1; s[nt][2] = p2; s[nt][3] = p3;
        }
#pragma unroll
        for (int off = 1; off <= 2; off <<= 1) {
            rs0 += __shfl_xor_sync(0xffffffffu, rs0, off);
            rs1 += __shfl_xor_sync(0xffffffffu, rs1, off);
        }
        li0 = li0 * al0 + rs0;
        li1 = li1 * al1 + rs1;
#pragma unroll
        for (int nt = 0; nt < 8; nt++) {
            o[nt][0] *= al0; o[nt][1] *= al0;
            o[nt][2] *= al1; o[nt][3] *= al1;
        }
        m0 = mn0; m1 = mn1;

        // ---- O += P V  (split: PhVh + PhVl + PlVh) ----
#pragma unroll
        for (int ks = 0; ks < 4; ks++) {
            int t0 = 2 * ks, t1 = 2 * ks + 1;
            uint32_t a0h, a0l, a1h, a1l, a2h, a2l, a3h, a3l;
            pack_hl(s[t0][0], s[t0][1], a0h, a0l);
            pack_hl(s[t0][2], s[t0][3], a1h, a1l);
            pack_hl(s[t1][0], s[t1][1], a2h, a2l);
            pack_hl(s[t1][2], s[t1][3], a3h, a3l);

            int key  = ks * 16 + (lane & 15);
            int dsub = (lane >> 4) << 3;
#pragma unroll
            for (int dblk = 0; dblk < 4; dblk++) {
                uint32_t off16 = (uint32_t)(key * FS + dblk * 16 + dsub) * 2;
                uint32_t vh0, vh1, vh2, vh3, vl0, vl1, vl2, vl3;
                ldmx4t(vh0, vh1, vh2, vh3, uVh + off16);
                ldmx4t(vl0, vl1, vl2, vl3, uVl + off16);
                mma16816(o[2 * dblk],     a0h, a1h, a2h, a3h, vh0, vh1);
                mma16816(o[2 * dblk],     a0h, a1h, a2h, a3h, vl0, vl1);
                mma16816(o[2 * dblk],     a0l, a1l, a2l, a3l, vh0, vh1);
                mma16816(o[2 * dblk + 1], a0h, a1h, a2h, a3h, vh2, vh3);
                mma16816(o[2 * dblk + 1], a0h, a1h, a2h, a3h, vl2, vl3);
                mma16816(o[2 * dblk + 1], a0l, a1l, a2l, a3l, vh2, vh3);
            }
        }
    }

    // ---- normalize + store ----
    const long obase = (long)b * bsO + (long)blockIdx.x * 64 * H_ + h * D_;
    float inv0 = 1.f / li0, inv1 = 1.f / li1;
    int row0 = wid * 16 + lr;
#pragma unroll
    for (int nt = 0; nt < 8; nt++) {
        int col = nt * 8 + lc;
        float2 o0 = {o[nt][0] * inv0, o[nt][1] * inv0};
        float2 o1 = {o[nt][2] * inv1, o[nt][3] * inv1};
        *reinterpret_cast<float2*>(O + obase + (long)row0 * H_ + col)       = o0;
        *reinterpret_cast<float2*>(O + obase + (long)(row0 + 8) * H_ + col) = o1;
    }
}

// ---------------- task-slice copies ----------------
__global__ __launch_bounds__(256) void copy_task(
    const float* __restrict__ q0, const float* __restrict__ k0,
    float* __restrict__ q1, float* __restrict__ k1, float* __restrict__ v1)
{
    int idx = blockIdx.x * blockDim.x + threadIdx.x;
    if (idx >= B_ * KL_ * H_) return;
    int b = idx / (KL_ * H_);
    int r = idx - b * (KL_ * H_);
    long src = (long)b * TOT_ * H_ + (long)MID_ * H_ + r;
    long dst = (long)b * TOT_ * H_ + r;
    float qv = q0[src];
    q1[dst] = qv;
    k1[dst] = k0[src];
    v1[dst] = qv;
}

// ---------------- launch ----------------
extern "C" void kernel_launch(void* const* d_in, const int* in_sizes, int n_in,
                              void* d_out, int out_size)
{
    const float* vis  = (const float*)d_in[0];
    const float* txt  = (const float*)d_in[1];
    const float* task = (const float*)d_in[2];
    const float* wq0  = (const float*)d_in[3];
    const float* bq0  = (const float*)d_in[4];
    const float* wk0  = (const float*)d_in[5];
    const float* bk0  = (const float*)d_in[6];
    const float* wv0  = (const float*)d_in[7];
    const float* bv0  = (const float*)d_in[8];
    const float* wq1  = (const float*)d_in[9];
    const float* bq1  = (const float*)d_in[10];
    const float* wk1  = (const float*)d_in[11];
    const float* bk1  = (const float*)d_in[12];
    const float* wv1  = (const float*)d_in[13];
    const float* bv1  = (const float*)d_in[14];
    const float* wo   = (const float*)d_in[15];
    const float* bo   = (const float*)d_in[16];
    float* out = (float*)d_out;

    float *q0, *k0, *v0, *mid, *q1, *k1, *v1, *ao;
    cudaGetSymbolAddress((void**)&q0,  g_q0);
    cudaGetSymbolAddress((void**)&k0,  g_k0);
    cudaGetSymbolAddress((void**)&v0,  g_v0);
    cudaGetSymbolAddress((void**)&mid, g_mid);
    cudaGetSymbolAddress((void**)&q1,  g_q1);
    cudaGetSymbolAddress((void**)&k1,  g_k1);
    cudaGetSymbolAddress((void**)&v1,  g_v1);
    cudaGetSymbolAddress((void**)&ao,  g_ao);

    __nv_bfloat16 *xh, *xl, *aoh, *aol, *wh, *wl;
    cudaGetSymbolAddress((void**)&xh,  g_xh);
    cudaGetSymbolAddress((void**)&xl,  g_xl);
    cudaGetSymbolAddress((void**)&aoh, g_aoh);
    cudaGetSymbolAddress((void**)&aol, g_aol);
    cudaGetSymbolAddress((void**)&wh,  g_wh);
    cudaGetSymbolAddress((void**)&wl,  g_wl);

    cudaFuncSetAttribute(gemm_mma,  cudaFuncAttributeMaxDynamicSharedMemorySize, GMMA_SMEM);
    cudaFuncSetAttribute(flash_mma, cudaFuncAttributeMaxDynamicSharedMemorySize, FLASH2_SMEM);

    const dim3 blk(256);
    const long TS = (long)TOT_ * H_;
    const long MS = (long)MID_ * H_;
    const float scale = 1.0f / 64.0f;
    const long WN4 = (long)H_ * H_ / 4;

    // 0) pack inputs to hi/lo bf16
    pack_gather_hilo<<<ROWS_ * H_ / 1024, blk>>>(vis, txt, task, xh, xl);
    pack_hilo<<<(int)(WN4 / 256), blk>>>(wq0, wh + 0L * H_ * H_, wl + 0L * H_ * H_, WN4);
    pack_hilo<<<(int)(WN4 / 256), blk>>>(wk0, wh + 1L * H_ * H_, wl + 1L * H_ * H_, WN4);
    pack_hilo<<<(int)(WN4 / 256), blk>>>(wv0, wh + 2L * H_ * H_, wl + 2L * H_ * H_, WN4);
    pack_hilo<<<(int)(WN4 / 256), blk>>>(wo,  wh + 3L * H_ * H_, wl + 3L * H_ * H_, WN4);

    // 1) QKV projections via split-bf16 HMMA GEMM
    {
        dim3 g(H_ / 128, ROWS_ / 128);
        gemm_mma<<<g, blk, GMMA_SMEM>>>(xh, xl, wh + 0L*H_*H_, wl + 0L*H_*H_, bq0, q0);
        gemm_mma<<<g, blk, GMMA_SMEM>>>(xh, xl, wh + 1L*H_*H_, wl + 1L*H_*H_, bk0, k0);
        gemm_mma<<<g, blk, GMMA_SMEM>>>(xh, xl, wh + 2L*H_*H_, wl + 2L*H_*H_, bv0, v0);
    }

    // 2) cross attentions -> mid
    flash_mma<<<dim3(VL_ / 64, B_ * NH_), 128, FLASH2_SMEM>>>(
        q0, k0 + (long)VL_ * H_, v0 + (long)VL_ * H_, mid,
        TS, TS, TS, MS, TL_, scale);
    flash_mma<<<dim3(TL_ / 64, B_ * NH_), 128, FLASH2_SMEM>>>(
        q0 + (long)VL_ * H_, k0, v0, mid + (long)VL_ * H_,
        TS, TS, TS, MS, VL_, scale);

    // 3) per-head D x D linears on mid -> q1/k1/v1 tokens [64..2560)
    {
        dim3 g(1, (MID_ * NH_) / 64, B_);
        long midB = (long)MID_ * H_;
        gemm64<false><<<g, blk>>>(mid, D_, midB, nullptr, nullptr, nullptr,
                                  wq1, bq1, q1 + (long)KL_ * H_, TS, D_, D_);
        gemm64<false><<<g, blk>>>(mid, D_, midB, nullptr, nullptr, nullptr,
                                  wk1, bk1, k1 + (long)KL_ * H_, TS, D_, D_);
        gemm64<false><<<g, blk>>>(mid, D_, midB, nullptr, nullptr, nullptr,
                                  wv1, bv1, v1 + (long)KL_ * H_, TS, D_, D_);
    }

    // 4) task slices
    copy_task<<<(B_ * KL_ * H_ + 255) / 256, blk>>>(q0, k0, q1, k1, v1);

    // 5) full attention
    flash_mma<<<dim3(TOT_ / 64, B_ * NH_), 128, FLASH2_SMEM>>>(
        q1, k1, v1, ao, TS, TS, TS, TS, TOT_, scale);

    // 6) output projection via HMMA
    pack_hilo<<<ROWS_ * H_ / 1024, blk>>>(ao, aoh, aol, (long)ROWS_ * H_ / 4);
    {
        dim3 g(H_ / 128, ROWS_ / 128);
        gemm_mma<<<g, blk, GMMA_SMEM>>>(aoh, aol, wh + 3L*H_*H_, wl + 3L*H_*H_, bo, out);
    }
}

// round 5
// speedup vs baseline: 4.7286x; 1.2973x over previous
#include <cuda_runtime.h>
#include <cuda_bf16.h>
#include <cstdint>

static constexpr int B_   = 2;
static constexpr int VL_  = 2048;
static constexpr int TL_  = 448;
static constexpr int KL_  = 64;
static constexpr int TOT_ = 2560;   // VL+TL+KL
static constexpr int MID_ = 2496;   // VL+TL
static constexpr int H_   = 1024;
static constexpr int NH_  = 16;
static constexpr int D_   = 64;
static constexpr int ROWS_ = B_ * TOT_;   // 5120

// ---------------- scratch (static device allocations) ----------------
__device__ float g_q0[B_*TOT_*H_];
__device__ float g_k0[B_*TOT_*H_];
__device__ float g_v0[B_*TOT_*H_];
__device__ float g_mid[B_*MID_*H_];
__device__ float g_q1[B_*TOT_*H_];
__device__ float g_k1[B_*TOT_*H_];
__device__ float g_v1[B_*TOT_*H_];
__device__ float g_ao[B_*TOT_*H_];

__device__ __nv_bfloat16 g_xh[ROWS_*H_];
__device__ __nv_bfloat16 g_xl[ROWS_*H_];
__device__ __nv_bfloat16 g_aoh[ROWS_*H_];
__device__ __nv_bfloat16 g_aol[ROWS_*H_];
__device__ __nv_bfloat16 g_wh[4][H_*H_];   // q0,k0,v0,o (contiguous!)
__device__ __nv_bfloat16 g_wl[4][H_*H_];

// ---------------- gather helper for the 3-way concat ----------------
__device__ __forceinline__ const float* gather_row(
    const float* __restrict__ v, const float* __restrict__ t,
    const float* __restrict__ k, int r)
{
    int b   = r / TOT_;
    int tok = r - b * TOT_;
    if (tok < VL_)  return v + (size_t)(b * VL_ + tok) * H_;
    if (tok < MID_) return t + (size_t)(b * TL_ + (tok - VL_)) * H_;
    return k + (size_t)(b * KL_ + (tok - MID_)) * H_;
}

// ---------------- hi/lo bf16 split helpers ----------------
__device__ __forceinline__ void split1(float x, __nv_bfloat16& h, __nv_bfloat16& l) {
    h = __float2bfloat16_rn(x);
    l = __float2bfloat16_rn(x - __bfloat162float(h));
}

__device__ __forceinline__ void split_store4(
    float4 x, __nv_bfloat16* ph, __nv_bfloat16* pl)
{
    __nv_bfloat16 h0,h1,h2,h3,l0,l1,l2,l3;
    split1(x.x,h0,l0); split1(x.y,h1,l1); split1(x.z,h2,l2); split1(x.w,h3,l3);
    *reinterpret_cast<__nv_bfloat162*>(ph)     = __halves2bfloat162(h0, h1);
    *reinterpret_cast<__nv_bfloat162*>(ph + 2) = __halves2bfloat162(h2, h3);
    *reinterpret_cast<__nv_bfloat162*>(pl)     = __halves2bfloat162(l0, l1);
    *reinterpret_cast<__nv_bfloat162*>(pl + 2) = __halves2bfloat162(l2, l3);
}

__device__ __forceinline__ void pack_hl(float x, float y, uint32_t& hi, uint32_t& lo) {
    __nv_bfloat162 h = __floats2bfloat162_rn(x, y);
    float hx = __bfloat162float(h.x), hy = __bfloat162float(h.y);
    __nv_bfloat162 l = __floats2bfloat162_rn(x - hx, y - hy);
    hi = *reinterpret_cast<uint32_t*>(&h);
    lo = *reinterpret_cast<uint32_t*>(&l);
}

__global__ __launch_bounds__(256) void pack_gather_hilo(
    const float* __restrict__ v, const float* __restrict__ t, const float* __restrict__ k,
    __nv_bfloat16* __restrict__ Xh, __nv_bfloat16* __restrict__ Xl)
{
    long i = (long)blockIdx.x * 256 + threadIdx.x;
    if (i >= (long)ROWS_ * H_ / 4) return;
    long e = i * 4;
    int r = (int)(e / H_);
    int c = (int)(e - (long)r * H_);
    const float* row = gather_row(v, t, k, r);
    float4 x = *reinterpret_cast<const float4*>(row + c);
    split_store4(x, Xh + e, Xl + e);
}

__global__ __launch_bounds__(256) void pack_hilo(
    const float* __restrict__ X,
    __nv_bfloat16* __restrict__ Xh, __nv_bfloat16* __restrict__ Xl, long n4)
{
    long i = (long)blockIdx.x * 256 + threadIdx.x;
    if (i >= n4) return;
    long e = i * 4;
    float4 x = *reinterpret_cast<const float4*>(X + e);
    split_store4(x, Xh + e, Xl + e);
}

// ---------------- mma.sync / ldmatrix / cp.async helpers ----------------
__device__ __forceinline__ void mma16816(
    float* c, uint32_t a0, uint32_t a1, uint32_t a2, uint32_t a3,
    uint32_t b0, uint32_t b1)
{
    asm volatile(
        "mma.sync.aligned.m16n8k16.row.col.f32.bf16.bf16.f32 "
        "{%0,%1,%2,%3}, {%4,%5,%6,%7}, {%8,%9}, {%0,%1,%2,%3};"
        : "+f"(c[0]), "+f"(c[1]), "+f"(c[2]), "+f"(c[3])
        : "r"(a0), "r"(a1), "r"(a2), "r"(a3), "r"(b0), "r"(b1));
}

__device__ __forceinline__ void ldmx4t(
    uint32_t& r0, uint32_t& r1, uint32_t& r2, uint32_t& r3, uint32_t addr)
{
    asm volatile(
        "ldmatrix.sync.aligned.m8n8.x4.trans.shared.b16 {%0,%1,%2,%3}, [%4];"
        : "=r"(r0), "=r"(r1), "=r"(r2), "=r"(r3) : "r"(addr));
}

__device__ __forceinline__ uint32_t smem_u32(const void* p) {
    uint32_t a;
    asm("{ .reg .u64 t; cvta.to.shared.u64 t, %1; cvt.u32.u64 %0, t; }" : "=r"(a) : "l"(p));
    return a;
}

__device__ __forceinline__ void cp16(uint32_t dst, const void* src) {
    asm volatile("cp.async.cg.shared.global [%0], [%1], 16;" :: "r"(dst), "l"(src));
}
#define CP_COMMIT() asm volatile("cp.async.commit_group;" ::: "memory")
#define CP_WAIT1()  asm volatile("cp.async.wait_group 1;" ::: "memory")
#define CP_WAIT0()  asm volatile("cp.async.wait_group 0;" ::: "memory")

// ---------------- split-bf16 HMMA GEMM, cp.async pipelined, fused outputs ----
// C[:,n] with n in [0,3072): output tensor = n/1024, col = n%1024.
// CTA tile 128x128, K-chunk 32, 256 threads (8 warps: 4m x 2n).
static constexpr int GS   = 40;
static constexpr int GTE  = 128 * GS;
static constexpr int GMMA_SMEM = 2 * 4 * GTE * 2;

__global__ __launch_bounds__(256) void gemm_mma(
    const __nv_bfloat16* __restrict__ Ah, const __nv_bfloat16* __restrict__ Al,
    const __nv_bfloat16* __restrict__ Bh, const __nv_bfloat16* __restrict__ Bl,
    const float* __restrict__ bias0, const float* __restrict__ bias1,
    const float* __restrict__ bias2,
    float* __restrict__ C0, float* __restrict__ C1, float* __restrict__ C2)
{
    constexpr int K = 1024;
    constexpr int NKC = K / 32;
    extern __shared__ __nv_bfloat16 sm[];
    const uint32_t smBase = smem_u32(sm);
    const int tid  = threadIdx.x;
    const int wid  = tid >> 5;
    const int lane = tid & 31;
    const int wm   = wid & 3;
    const int wn   = wid >> 2;
    const int m0   = blockIdx.y * 128;
    const int n0   = blockIdx.x * 128;           // global over (up to) 3072

    const int which = blockIdx.x >> 3;           // 8 n-blocks per 1024-col output
    const float* bias = which == 0 ? bias0 : (which == 1 ? bias1 : bias2);
    float* C           = which == 0 ? C0    : (which == 1 ? C1    : C2);
    const int col0 = (blockIdx.x & 7) * 128;

    const __nv_bfloat16* gAh = Ah + (long)m0 * K;
    const __nv_bfloat16* gAl = Al + (long)m0 * K;
    const __nv_bfloat16* gBh = Bh + (long)n0 * K;
    const __nv_bfloat16* gBl = Bl + (long)n0 * K;

    float acc[2][8][4];
#pragma unroll
    for (int mt = 0; mt < 2; mt++)
#pragma unroll
        for (int nt = 0; nt < 8; nt++)
#pragma unroll
            for (int j = 0; j < 4; j++) acc[mt][nt][j] = 0.f;

    auto load_stage = [&](int buf, int kc) {
        uint32_t su = smBase + (uint32_t)buf * 4 * GTE * 2;
#pragma unroll
        for (int i = 0; i < 2; i++) {
            int e   = i * 256 + tid;
            int r   = e >> 2;
            int sg  = e & 3;
            long go = (long)r * K + kc * 32 + sg * 8;
            uint32_t so = (uint32_t)(r * GS + sg * 8) * 2;
            cp16(su + so,               gAh + go);
            cp16(su + GTE * 2 + so,     gAl + go);
            cp16(su + 2 * GTE * 2 + so, gBh + go);
            cp16(su + 3 * GTE * 2 + so, gBl + go);
        }
    };

    const int lr = lane >> 2;
    const int lc = (lane & 3) * 2;

    load_stage(0, 0);
    CP_COMMIT();

    for (int kc = 0; kc < NKC; kc++) {
        int p = kc & 1;
        if (kc + 1 < NKC) {
            load_stage(1 - p, kc + 1);
            CP_COMMIT();
            CP_WAIT1();
        } else {
            CP_WAIT0();
        }
        __syncthreads();

        const __nv_bfloat16* sAH = sm + p * 4 * GTE;
        const __nv_bfloat16* sAL = sAH + GTE;
        const __nv_bfloat16* sBH = sAH + 2 * GTE;
        const __nv_bfloat16* sBL = sAH + 3 * GTE;

#pragma unroll
        for (int h = 0; h < 32; h += 16) {
            uint32_t aH[2][4], aL[2][4];
#pragma unroll
            for (int mt = 0; mt < 2; mt++) {
                int rb = (wm * 32 + mt * 16 + lr) * GS + h + lc;
                aH[mt][0] = *reinterpret_cast<const uint32_t*>(sAH + rb);
                aH[mt][1] = *reinterpret_cast<const uint32_t*>(sAH + rb + 8 * GS);
                aH[mt][2] = *reinterpret_cast<const uint32_t*>(sAH + rb + 8);
                aH[mt][3] = *reinterpret_cast<const uint32_t*>(sAH + rb + 8 * GS + 8);
                aL[mt][0] = *reinterpret_cast<const uint32_t*>(sAL + rb);
                aL[mt][1] = *reinterpret_cast<const uint32_t*>(sAL + rb + 8 * GS);
                aL[mt][2] = *reinterpret_cast<const uint32_t*>(sAL + rb + 8);
                aL[mt][3] = *reinterpret_cast<const uint32_t*>(sAL + rb + 8 * GS + 8);
            }
            uint32_t bb[8][2];
#pragma unroll
            for (int nt = 0; nt < 8; nt++) {
                int nb = (wn * 64 + nt * 8 + lr) * GS + h + lc;
                bb[nt][0] = *reinterpret_cast<const uint32_t*>(sBH + nb);
                bb[nt][1] = *reinterpret_cast<const uint32_t*>(sBH + nb + 8);
            }
#pragma unroll
            for (int mt = 0; mt < 2; mt++)
#pragma unroll
                for (int nt = 0; nt < 8; nt++)
                    mma16816(acc[mt][nt], aH[mt][0], aH[mt][1], aH[mt][2], aH[mt][3],
                             bb[nt][0], bb[nt][1]);
#pragma unroll
            for (int mt = 0; mt < 2; mt++)
#pragma unroll
                for (int nt = 0; nt < 8; nt++)
                    mma16816(acc[mt][nt], aL[mt][0], aL[mt][1], aL[mt][2], aL[mt][3],
                             bb[nt][0], bb[nt][1]);
#pragma unroll
            for (int nt = 0; nt < 8; nt++) {
                int nb = (wn * 64 + nt * 8 + lr) * GS + h + lc;
                bb[nt][0] = *reinterpret_cast<const uint32_t*>(sBL + nb);
                bb[nt][1] = *reinterpret_cast<const uint32_t*>(sBL + nb + 8);
            }
#pragma unroll
            for (int mt = 0; mt < 2; mt++)
#pragma unroll
                for (int nt = 0; nt < 8; nt++)
                    mma16816(acc[mt][nt], aH[mt][0], aH[mt][1], aH[mt][2], aH[mt][3],
                             bb[nt][0], bb[nt][1]);
        }
        __syncthreads();
    }

#pragma unroll
    for (int mt = 0; mt < 2; mt++) {
        int row0 = m0 + wm * 32 + mt * 16 + lr;
#pragma unroll
        for (int nt = 0; nt < 8; nt++) {
            int col = col0 + wn * 64 + nt * 8 + lc;
            float2 bv = *reinterpret_cast<const float2*>(bias + col);
            float2 o0 = {acc[mt][nt][0] + bv.x, acc[mt][nt][1] + bv.y};
            float2 o1 = {acc[mt][nt][2] + bv.x, acc[mt][nt][3] + bv.y};
            *reinterpret_cast<float2*>(C + (long)row0 * 1024 + col)       = o0;
            *reinterpret_cast<float2*>(C + (long)(row0 + 8) * 1024 + col) = o1;
        }
    }
}

// ---------------- per-head DxD linears (q1/k1/v1 share the A tile) --------
// mid is a contiguous [B*MID*NH, 64] fp32 matrix. Out col n uses W[n, k].
// CTA: 64 rows, 4 warps (16 rows each), 3 outputs computed from one A tile.
static constexpr int PS = 72;
static constexpr int PH_SMEM = 8 * 64 * PS * 2;   // 6 W tiles + A hi/lo = 73728 B

__global__ __launch_bounds__(128) void gemm_ph(
    const float* __restrict__ mid,
    const float* __restrict__ wq, const float* __restrict__ wk, const float* __restrict__ wv,
    const float* __restrict__ bq, const float* __restrict__ bk, const float* __restrict__ bv,
    float* __restrict__ q1, float* __restrict__ k1, float* __restrict__ v1)
{
    extern __shared__ __nv_bfloat16 sp[];
    __nv_bfloat16* Ah = sp + 6 * 64 * PS;
    __nv_bfloat16* Al = sp + 7 * 64 * PS;

    const int tid  = threadIdx.x;
    const int wid  = tid >> 5;
    const int lane = tid & 31;
    const int lr   = lane >> 2;
    const int lc   = (lane & 3) * 2;

    const float* Ws[3] = {wq, wk, wv};
#pragma unroll
    for (int o = 0; o < 3; o++) {
        __nv_bfloat16* Wh = sp + (2 * o)     * 64 * PS;
        __nv_bfloat16* Wl = sp + (2 * o + 1) * 64 * PS;
#pragma unroll
        for (int i = 0; i < 8; i++) {
            int e = i * 128 + tid;
            int r = e >> 4, c = (e & 15) * 4;
            float4 x = *reinterpret_cast<const float4*>(Ws[o] + r * 64 + c);
            split_store4(x, Wh + r * PS + c, Wl + r * PS + c);
        }
    }
    const long abase = (long)blockIdx.x * 64 * 64;
#pragma unroll
    for (int i = 0; i < 8; i++) {
        int e = i * 128 + tid;
        int r = e >> 4, c = (e & 15) * 4;
        float4 x = *reinterpret_cast<const float4*>(mid + abase + r * 64 + c);
        split_store4(x, Ah + r * PS + c, Al + r * PS + c);
    }
    __syncthreads();

    uint32_t aH[4][4], aL[4][4];
#pragma unroll
    for (int ks = 0; ks < 4; ks++) {
        int ab = (wid * 16 + lr) * PS + ks * 16 + lc;
        aH[ks][0] = *reinterpret_cast<const uint32_t*>(Ah + ab);
        aH[ks][1] = *reinterpret_cast<const uint32_t*>(Ah + ab + 8 * PS);
        aH[ks][2] = *reinterpret_cast<const uint32_t*>(Ah + ab + 8);
        aH[ks][3] = *reinterpret_cast<const uint32_t*>(Ah + ab + 8 * PS + 8);
        aL[ks][0] = *reinterpret_cast<const uint32_t*>(Al + ab);
        aL[ks][1] = *reinterpret_cast<const uint32_t*>(Al + ab + 8 * PS);
        aL[ks][2] = *reinterpret_cast<const uint32_t*>(Al + ab + 8);
        aL[ks][3] = *reinterpret_cast<const uint32_t*>(Al + ab + 8 * PS + 8);
    }

    float acc[3][8][4];
#pragma unroll
    for (int o = 0; o < 3; o++)
#pragma unroll
        for (int nt = 0; nt < 8; nt++)
#pragma unroll
            for (int j = 0; j < 4; j++) acc[o][nt][j] = 0.f;

#pragma unroll
    for (int o = 0; o < 3; o++) {
        const __nv_bfloat16* Wh = sp + (2 * o)     * 64 * PS;
        const __nv_bfloat16* Wl = sp + (2 * o + 1) * 64 * PS;
#pragma unroll
        for (int ks = 0; ks < 4; ks++)
#pragma unroll
            for (int nt = 0; nt < 8; nt++) {
                int nb = (nt * 8 + lr) * PS + ks * 16 + lc;
                uint32_t bh0 = *reinterpret_cast<const uint32_t*>(Wh + nb);
                uint32_t bh1 = *reinterpret_cast<const uint32_t*>(Wh + nb + 8);
                uint32_t bl0 = *reinterpret_cast<const uint32_t*>(Wl + nb);
                uint32_t bl1 = *reinterpret_cast<const uint32_t*>(Wl + nb + 8);
                mma16816(acc[o][nt], aH[ks][0], aH[ks][1], aH[ks][2], aH[ks][3], bh0, bh1);
                mma16816(acc[o][nt], aH[ks][0], aH[ks][1], aH[ks][2], aH[ks][3], bl0, bl1);
                mma16816(acc[o][nt], aL[ks][0], aL[ks][1], aL[ks][2], aL[ks][3], bh0, bh1);
            }
    }

    // write: row r of flattened [B*MID*NH, 64] -> out + b*TS + KL*H + rr*64
    float* outs[3] = {q1, k1, v1};
    const float* biases[3] = {bq, bk, bv};
    const long TS = (long)TOT_ * H_;
    int r0 = blockIdx.x * 64 + wid * 16 + lr;
#pragma unroll
    for (int half = 0; half < 2; half++) {
        int r = r0 + half * 8;
        int b = r / (MID_ * NH_);
        int rr = r - b * (MID_ * NH_);
        long off = (long)b * TS + (long)KL_ * H_ + (long)rr * 64;
#pragma unroll
        for (int o = 0; o < 3; o++) {
#pragma unroll
            for (int nt = 0; nt < 8; nt++) {
                int col = nt * 8 + lc;
                float2 bv2 = *reinterpret_cast<const float2*>(biases[o] + col);
                float2 ov;
                ov.x = acc[o][nt][half * 2 + 0] + bv2.x;
                ov.y = acc[o][nt][half * 2 + 1] + bv2.y;
                *reinterpret_cast<float2*>(outs[o] + off + col) = ov;
            }
        }
    }
}

// ---------------- Flash attention on tensor cores (unchanged from R4) -----
static constexpr int FS = 72;
static constexpr int FLASH2_SMEM = 6 * 64 * FS * 2;   // 55296 B

__global__ __launch_bounds__(128) void flash_mma(
    const float* __restrict__ Q, const float* __restrict__ K,
    const float* __restrict__ V, float* __restrict__ O,
    long bsQ, long bsK, long bsV, long bsO,
    int klen, float scale)
{
    extern __shared__ __nv_bfloat16 sb[];
    __nv_bfloat16* Qh = sb;
    __nv_bfloat16* Ql = sb + 64 * FS;
    __nv_bfloat16* Kh = sb + 2 * 64 * FS;
    __nv_bfloat16* Kl = sb + 3 * 64 * FS;
    __nv_bfloat16* Vh = sb + 4 * 64 * FS;
    __nv_bfloat16* Vl = sb + 5 * 64 * FS;

    const int tid  = threadIdx.x;
    const int wid  = tid >> 5;
    const int lane = tid & 31;
    const int lr   = lane >> 2;
    const int lc   = (lane & 3) * 2;
    const int b    = blockIdx.y >> 4;
    const int h    = blockIdx.y & 15;

    const uint32_t uVh = smem_u32(Vh);
    const uint32_t uVl = smem_u32(Vl);

    const long qbase = (long)b * bsQ + (long)blockIdx.x * 64 * H_ + h * D_;
#pragma unroll
    for (int i = 0; i < 8; i++) {
        int e = i * 128 + tid;
        int r = e >> 4, c = (e & 15) * 4;
        float4 x = *reinterpret_cast<const float4*>(Q + qbase + (long)r * H_ + c);
        split_store4(x, Qh + r * FS + c, Ql + r * FS + c);
    }

    float m0 = -1e30f, m1 = -1e30f, li0 = 0.f, li1 = 0.f;
    float o[8][4];
#pragma unroll
    for (int nt = 0; nt < 8; nt++)
#pragma unroll
        for (int j = 0; j < 4; j++) o[nt][j] = 0.f;

    const long kb = (long)b * bsK + h * D_;
    const long vb = (long)b * bsV + h * D_;
    const int ntiles = klen >> 6;

    for (int kt = 0; kt < ntiles; kt++) {
        __syncthreads();
#pragma unroll
        for (int i = 0; i < 8; i++) {
            int e = i * 128 + tid;
            int r = e >> 4, c = (e & 15) * 4;
            long go = (long)(kt * 64 + r) * H_ + c;
            float4 xk = *reinterpret_cast<const float4*>(K + kb + go);
            split_store4(xk, Kh + r * FS + c, Kl + r * FS + c);
            float4 xv = *reinterpret_cast<const float4*>(V + vb + go);
            split_store4(xv, Vh + r * FS + c, Vl + r * FS + c);
        }
        __syncthreads();

        float s[8][4];
#pragma unroll
        for (int nt = 0; nt < 8; nt++)
#pragma unroll
            for (int j = 0; j < 4; j++) s[nt][j] = 0.f;

#pragma unroll
        for (int ks = 0; ks < 4; ks++) {
            int ab = (wid * 16 + lr) * FS + ks * 16 + lc;
            uint32_t aH0 = *reinterpret_cast<const uint32_t*>(Qh + ab);
            uint32_t aH1 = *reinterpret_cast<const uint32_t*>(Qh + ab + 8 * FS);
            uint32_t aH2 = *reinterpret_cast<const uint32_t*>(Qh + ab + 8);
            uint32_t aH3 = *reinterpret_cast<const uint32_t*>(Qh + ab + 8 * FS + 8);
            uint32_t aL0 = *reinterpret_cast<const uint32_t*>(Ql + ab);
            uint32_t aL1 = *reinterpret_cast<const uint32_t*>(Ql + ab + 8 * FS);
            uint32_t aL2 = *reinterpret_cast<const uint32_t*>(Ql + ab + 8);
            uint32_t aL3 = *reinterpret_cast<const uint32_t*>(Ql + ab + 8 * FS + 8);
#pragma unroll
            for (int nt = 0; nt < 8; nt++) {
                int nb = (nt * 8 + lr) * FS + ks * 16 + lc;
                uint32_t bh0 = *reinterpret_cast<const uint32_t*>(Kh + nb);
                uint32_t bh1 = *reinterpret_cast<const uint32_t*>(Kh + nb + 8);
                uint32_t bl0 = *reinterpret_cast<const uint32_t*>(Kl + nb);
                uint32_t bl1 = *reinterpret_cast<const uint32_t*>(Kl + nb + 8);
                mma16816(s[nt], aH0, aH1, aH2, aH3, bh0, bh1);
                mma16816(s[nt], aH0, aH1, aH2, aH3, bl0, bl1);
                mma16816(s[nt], aL0, aL1, aL2, aL3, bh0, bh1);
            }
        }

        float rm0 = -1e30f, rm1 = -1e30f;
#pragma unroll
        for (int nt = 0; nt < 8; nt++) {
            rm0 = fmaxf(rm0, fmaxf(s[nt][0], s[nt][1]));
            rm1 = fmaxf(rm1, fmaxf(s[nt][2], s[nt][3]));
        }
        rm0 *= scale; rm1 *= scale;
#pragma unroll
        for (int off = 1; off <= 2; off <<= 1) {
            rm0 = fmaxf(rm0, __shfl_xor_sync(0xffffffffu, rm0, off));
            rm1 = fmaxf(rm1, __shfl_xor_sync(0xffffffffu, rm1, off));
        }
        float mn0 = fmaxf(m0, rm0), mn1 = fmaxf(m1, rm1);
        float al0 = __expf(m0 - mn0), al1 = __expf(m1 - mn1);

        float rs0 = 0.f, rs1 = 0.f;
#pragma unroll
        for (int nt = 0; nt < 8; nt++) {
            float p0 = __expf(fmaf(s[nt][0], scale, -mn0));
            float p1 = __expf(fmaf(s[nt][1], scale, -mn0));
            float p2 = __expf(fmaf(s[nt][2], scale, -mn1));
            float p3 = __expf(fmaf(s[nt][3], scale, -mn1));
            rs0 += p0 + p1; rs1 += p2 + p3;
            s[nt][0] = p0; s[nt][1] = p1; s[nt][2] = p2; s[nt][3] = p3;
        }
#pragma unroll
        for (int off = 1; off <= 2; off <<= 1) {
            rs0 += __shfl_xor_sync(0xffffffffu, rs0, off);
            rs1 += __shfl_xor_sync(0xffffffffu, rs1, off);
        }
        li0 = li0 * al0 + rs0;
        li1 = li1 * al1 + rs1;
#pragma unroll
        for (int nt = 0; nt < 8; nt++) {
            o[nt][0] *= al0; o[nt][1] *= al0;
            o[nt][2] *= al1; o[nt][3] *= al1;
        }
        m0 = mn0; m1 = mn1;

#pragma unroll
        for (int ks = 0; ks < 4; ks++) {
            int t0 = 2 * ks, t1 = 2 * ks + 1;
            uint32_t a0h, a0l, a1h, a1l, a2h, a2l, a3h, a3l;
            pack_hl(s[t0][0], s[t0][1], a0h, a0l);
            pack_hl(s[t0][2], s[t0][3], a1h, a1l);
            pack_hl(s[t1][0], s[t1][1], a2h, a2l);
            pack_hl(s[t1][2], s[t1][3], a3h, a3l);

            int key  = ks * 16 + (lane & 15);
            int dsub = (lane >> 4) << 3;
#pragma unroll
            for (int dblk = 0; dblk < 4; dblk++) {
                uint32_t off16 = (uint32_t)(key * FS + dblk * 16 + dsub) * 2;
                uint32_t vh0, vh1, vh2, vh3, vl0, vl1, vl2, vl3;
                ldmx4t(vh0, vh1, vh2, vh3, uVh + off16);
                ldmx4t(vl0, vl1, vl2, vl3, uVl + off16);
                mma16816(o[2 * dblk],     a0h, a1h, a2h, a3h, vh0, vh1);
                mma16816(o[2 * dblk],     a0h, a1h, a2h, a3h, vl0, vl1);
                mma16816(o[2 * dblk],     a0l, a1l, a2l, a3l, vh0, vh1);
                mma16816(o[2 * dblk + 1], a0h, a1h, a2h, a3h, vh2, vh3);
                mma16816(o[2 * dblk + 1], a0h, a1h, a2h, a3h, vl2, vl3);
                mma16816(o[2 * dblk + 1], a0l, a1l, a2l, a3l, vh2, vh3);
            }
        }
    }

    const long obase = (long)b * bsO + (long)blockIdx.x * 64 * H_ + h * D_;
    float inv0 = 1.f / li0, inv1 = 1.f / li1;
    int row0 = wid * 16 + lr;
#pragma unroll
    for (int nt = 0; nt < 8; nt++) {
        int col = nt * 8 + lc;
        float2 o0 = {o[nt][0] * inv0, o[nt][1] * inv0};
        float2 o1 = {o[nt][2] * inv1, o[nt][3] * inv1};
        *reinterpret_cast<float2*>(O + obase + (long)row0 * H_ + col)       = o0;
        *reinterpret_cast<float2*>(O + obase + (long)(row0 + 8) * H_ + col) = o1;
    }
}

// ---------------- task-slice copies ----------------
__global__ __launch_bounds__(256) void copy_task(
    const float* __restrict__ q0, const float* __restrict__ k0,
    float* __restrict__ q1, float* __restrict__ k1, float* __restrict__ v1)
{
    int idx = blockIdx.x * blockDim.x + threadIdx.x;
    if (idx >= B_ * KL_ * H_) return;
    int b = idx / (KL_ * H_);
    int r = idx - b * (KL_ * H_);
    long src = (long)b * TOT_ * H_ + (long)MID_ * H_ + r;
    long dst = (long)b * TOT_ * H_ + r;
    float qv = q0[src];
    q1[dst] = qv;
    k1[dst] = k0[src];
    v1[dst] = qv;
}

// ---------------- launch ----------------
extern "C" void kernel_launch(void* const* d_in, const int* in_sizes, int n_in,
                              void* d_out, int out_size)
{
    const float* vis  = (const float*)d_in[0];
    const float* txt  = (const float*)d_in[1];
    const float* task = (const float*)d_in[2];
    const float* wq0  = (const float*)d_in[3];
    const float* bq0  = (const float*)d_in[4];
    const float* wk0  = (const float*)d_in[5];
    const float* bk0  = (const float*)d_in[6];
    const float* wv0  = (const float*)d_in[7];
    const float* bv0  = (const float*)d_in[8];
    const float* wq1  = (const float*)d_in[9];
    const float* bq1  = (const float*)d_in[10];
    const float* wk1  = (const float*)d_in[11];
    const float* bk1  = (const float*)d_in[12];
    const float* wv1  = (const float*)d_in[13];
    const float* bv1  = (const float*)d_in[14];
    const float* wo   = (const float*)d_in[15];
    const float* bo   = (const float*)d_in[16];
    float* out = (float*)d_out;

    float *q0, *k0, *v0, *mid, *q1, *k1, *v1, *ao;
    cudaGetSymbolAddress((void**)&q0,  g_q0);
    cudaGetSymbolAddress((void**)&k0,  g_k0);
    cudaGetSymbolAddress((void**)&v0,  g_v0);
    cudaGetSymbolAddress((void**)&mid, g_mid);
    cudaGetSymbolAddress((void**)&q1,  g_q1);
    cudaGetSymbolAddress((void**)&k1,  g_k1);
    cudaGetSymbolAddress((void**)&v1,  g_v1);
    cudaGetSymbolAddress((void**)&ao,  g_ao);

    __nv_bfloat16 *xh, *xl, *aoh, *aol, *wh, *wl;
    cudaGetSymbolAddress((void**)&xh,  g_xh);
    cudaGetSymbolAddress((void**)&xl,  g_xl);
    cudaGetSymbolAddress((void**)&aoh, g_aoh);
    cudaGetSymbolAddress((void**)&aol, g_aol);
    cudaGetSymbolAddress((void**)&wh,  g_wh);
    cudaGetSymbolAddress((void**)&wl,  g_wl);

    cudaFuncSetAttribute(gemm_mma,  cudaFuncAttributeMaxDynamicSharedMemorySize, GMMA_SMEM);
    cudaFuncSetAttribute(flash_mma, cudaFuncAttributeMaxDynamicSharedMemorySize, FLASH2_SMEM);
    cudaFuncSetAttribute(gemm_ph,   cudaFuncAttributeMaxDynamicSharedMemorySize, PH_SMEM);

    const dim3 blk(256);
    const long TS = (long)TOT_ * H_;
    const long MS = (long)MID_ * H_;
    const float scale = 1.0f / 64.0f;
    const long WN4 = (long)H_ * H_ / 4;

    // 0) pack inputs to hi/lo bf16
    pack_gather_hilo<<<ROWS_ * H_ / 1024, blk>>>(vis, txt, task, xh, xl);
    pack_hilo<<<(int)(WN4 / 256), blk>>>(wq0, wh + 0L * H_ * H_, wl + 0L * H_ * H_, WN4);
    pack_hilo<<<(int)(WN4 / 256), blk>>>(wk0, wh + 1L * H_ * H_, wl + 1L * H_ * H_, WN4);
    pack_hilo<<<(int)(WN4 / 256), blk>>>(wv0, wh + 2L * H_ * H_, wl + 2L * H_ * H_, WN4);
    pack_hilo<<<(int)(WN4 / 256), blk>>>(wo,  wh + 3L * H_ * H_, wl + 3L * H_ * H_, WN4);

    // 1) fused QKV projection: one launch, N = 3072 (weights contiguous)
    {
        dim3 g(3 * H_ / 128, ROWS_ / 128);
        gemm_mma<<<g, blk, GMMA_SMEM>>>(xh, xl, wh, wl,
                                        bq0, bk0, bv0, q0, k0, v0);
    }

    // 2) cross attentions -> mid
    flash_mma<<<dim3(VL_ / 64, B_ * NH_), 128, FLASH2_SMEM>>>(
        q0, k0 + (long)VL_ * H_, v0 + (long)VL_ * H_, mid,
        TS, TS, TS, MS, TL_, scale);
    flash_mma<<<dim3(TL_ / 64, B_ * NH_), 128, FLASH2_SMEM>>>(
        q0 + (long)VL_ * H_, k0, v0, mid + (long)VL_ * H_,
        TS, TS, TS, MS, VL_, scale);

    // 3) per-head D x D linears on mid -> q1/k1/v1 tokens [64..2560)
    gemm_ph<<<(B_ * MID_ * NH_) / 64, 128, PH_SMEM>>>(
        mid, wq1, wk1, wv1, bq1, bk1, bv1, q1, k1, v1);

    // 4) task slices
    copy_task<<<(B_ * KL_ * H_ + 255) / 256, blk>>>(q0, k0, q1, k1, v1);

    // 5) full attention
    flash_mma<<<dim3(TOT_ / 64, B_ * NH_), 128, FLASH2_SMEM>>>(
        q1, k1, v1, ao, TS, TS, TS, TS, TOT_, scale);

    // 6) output projection
    pack_hilo<<<ROWS_ * H_ / 1024, blk>>>(ao, aoh, aol, (long)ROWS_ * H_ / 4);
    {
        dim3 g(H_ / 128, ROWS_ / 128);
        gemm_mma<<<g, blk, GMMA_SMEM>>>(aoh, aol, wh + 3L*H_*H_, wl + 3L*H_*H_,
                                        bo, bo, bo, out, out, out);
    }
}

// round 6
// speedup vs baseline: 4.7308x; 1.0005x over previous
#include <cuda_runtime.h>
#include <cuda_bf16.h>
#include <cstdint>

static constexpr int B_   = 2;
static constexpr int VL_  = 2048;
static constexpr int TL_  = 448;
static constexpr int KL_  = 64;
static constexpr int TOT_ = 2560;   // VL+TL+KL
static constexpr int MID_ = 2496;   // VL+TL
static constexpr int H_   = 1024;
static constexpr int NH_  = 16;
static constexpr int D_   = 64;
static constexpr int ROWS_ = B_ * TOT_;   // 5120

// ---------------- scratch (static device allocations) ----------------
__device__ float g_mid[B_*MID_*H_];

__device__ __nv_bfloat16 g_xh[ROWS_*H_];
__device__ __nv_bfloat16 g_xl[ROWS_*H_];
__device__ __nv_bfloat16 g_aoh[ROWS_*H_];
__device__ __nv_bfloat16 g_aol[ROWS_*H_];
__device__ __nv_bfloat16 g_wh[4][H_*H_];   // q0,k0,v0,o (contiguous)
__device__ __nv_bfloat16 g_wl[4][H_*H_];

__device__ __nv_bfloat16 g_q0h[ROWS_*H_], g_q0l[ROWS_*H_];
__device__ __nv_bfloat16 g_k0h[ROWS_*H_], g_k0l[ROWS_*H_];
__device__ __nv_bfloat16 g_v0h[ROWS_*H_], g_v0l[ROWS_*H_];
__device__ __nv_bfloat16 g_q1h[ROWS_*H_], g_q1l[ROWS_*H_];
__device__ __nv_bfloat16 g_k1h[ROWS_*H_], g_k1l[ROWS_*H_];
__device__ __nv_bfloat16 g_v1h[ROWS_*H_], g_v1l[ROWS_*H_];

// ---------------- gather helper for the 3-way concat ----------------
__device__ __forceinline__ const float* gather_row(
    const float* __restrict__ v, const float* __restrict__ t,
    const float* __restrict__ k, int r)
{
    int b   = r / TOT_;
    int tok = r - b * TOT_;
    if (tok < VL_)  return v + (size_t)(b * VL_ + tok) * H_;
    if (tok < MID_) return t + (size_t)(b * TL_ + (tok - VL_)) * H_;
    return k + (size_t)(b * KL_ + (tok - MID_)) * H_;
}

// ---------------- hi/lo bf16 split helpers ----------------
__device__ __forceinline__ void split1(float x, __nv_bfloat16& h, __nv_bfloat16& l) {
    h = __float2bfloat16_rn(x);
    l = __float2bfloat16_rn(x - __bfloat162float(h));
}

__device__ __forceinline__ void split_store4(
    float4 x, __nv_bfloat16* ph, __nv_bfloat16* pl)
{
    __nv_bfloat16 h0,h1,h2,h3,l0,l1,l2,l3;
    split1(x.x,h0,l0); split1(x.y,h1,l1); split1(x.z,h2,l2); split1(x.w,h3,l3);
    *reinterpret_cast<__nv_bfloat162*>(ph)     = __halves2bfloat162(h0, h1);
    *reinterpret_cast<__nv_bfloat162*>(ph + 2) = __halves2bfloat162(h2, h3);
    *reinterpret_cast<__nv_bfloat162*>(pl)     = __halves2bfloat162(l0, l1);
    *reinterpret_cast<__nv_bfloat162*>(pl + 2) = __halves2bfloat162(l2, l3);
}

__device__ __forceinline__ void pack_hl(float x, float y, uint32_t& hi, uint32_t& lo) {
    __nv_bfloat162 h = __floats2bfloat162_rn(x, y);
    float hx = __bfloat162float(h.x), hy = __bfloat162float(h.y);
    __nv_bfloat162 l = __floats2bfloat162_rn(x - hx, y - hy);
    hi = *reinterpret_cast<uint32_t*>(&h);
    lo = *reinterpret_cast<uint32_t*>(&l);
}

__global__ __launch_bounds__(256) void pack_gather_hilo(
    const float* __restrict__ v, const float* __restrict__ t, const float* __restrict__ k,
    __nv_bfloat16* __restrict__ Xh, __nv_bfloat16* __restrict__ Xl)
{
    long i = (long)blockIdx.x * 256 + threadIdx.x;
    if (i >= (long)ROWS_ * H_ / 4) return;
    long e = i * 4;
    int r = (int)(e / H_);
    int c = (int)(e - (long)r * H_);
    const float* row = gather_row(v, t, k, r);
    float4 x = *reinterpret_cast<const float4*>(row + c);
    split_store4(x, Xh + e, Xl + e);
}

__global__ __launch_bounds__(256) void pack_hilo(
    const float* __restrict__ X,
    __nv_bfloat16* __restrict__ Xh, __nv_bfloat16* __restrict__ Xl, long n4)
{
    long i = (long)blockIdx.x * 256 + threadIdx.x;
    if (i >= n4) return;
    long e = i * 4;
    float4 x = *reinterpret_cast<const float4*>(X + e);
    split_store4(x, Xh + e, Xl + e);
}

// ---------------- mma.sync / ldmatrix / cp.async helpers ----------------
__device__ __forceinline__ void mma16816(
    float* c, uint32_t a0, uint32_t a1, uint32_t a2, uint32_t a3,
    uint32_t b0, uint32_t b1)
{
    asm volatile(
        "mma.sync.aligned.m16n8k16.row.col.f32.bf16.bf16.f32 "
        "{%0,%1,%2,%3}, {%4,%5,%6,%7}, {%8,%9}, {%0,%1,%2,%3};"
        : "+f"(c[0]), "+f"(c[1]), "+f"(c[2]), "+f"(c[3])
        : "r"(a0), "r"(a1), "r"(a2), "r"(a3), "r"(b0), "r"(b1));
}

__device__ __forceinline__ void ldmx4t(
    uint32_t& r0, uint32_t& r1, uint32_t& r2, uint32_t& r3, uint32_t addr)
{
    asm volatile(
        "ldmatrix.sync.aligned.m8n8.x4.trans.shared.b16 {%0,%1,%2,%3}, [%4];"
        : "=r"(r0), "=r"(r1), "=r"(r2), "=r"(r3) : "r"(addr));
}

__device__ __forceinline__ uint32_t smem_u32(const void* p) {
    uint32_t a;
    asm("{ .reg .u64 t; cvta.to.shared.u64 t, %1; cvt.u32.u64 %0, t; }" : "=r"(a) : "l"(p));
    return a;
}

__device__ __forceinline__ void cp16(uint32_t dst, const void* src) {
    asm volatile("cp.async.cg.shared.global [%0], [%1], 16;" :: "r"(dst), "l"(src));
}
#define CP_COMMIT() asm volatile("cp.async.commit_group;" ::: "memory")
#define CP_WAIT1()  asm volatile("cp.async.wait_group 1;" ::: "memory")
#define CP_WAIT0()  asm volatile("cp.async.wait_group 0;" ::: "memory")

// ---------------- split-bf16 HMMA GEMM, cp.async pipelined ----------------
// MODE 0: fp32 C0 output. MODE 1: hi/lo bf16 outputs selected by n-block.
static constexpr int GS   = 40;
static constexpr int GTE  = 128 * GS;
static constexpr int GMMA_SMEM = 2 * 4 * GTE * 2;

template<int MODE>
__global__ __launch_bounds__(256) void gemm_mma(
    const __nv_bfloat16* __restrict__ Ah, const __nv_bfloat16* __restrict__ Al,
    const __nv_bfloat16* __restrict__ Bh, const __nv_bfloat16* __restrict__ Bl,
    const float* __restrict__ bias0, const float* __restrict__ bias1,
    const float* __restrict__ bias2,
    float* __restrict__ C0,
    __nv_bfloat16* __restrict__ H0, __nv_bfloat16* __restrict__ L0,
    __nv_bfloat16* __restrict__ H1, __nv_bfloat16* __restrict__ L1,
    __nv_bfloat16* __restrict__ H2, __nv_bfloat16* __restrict__ L2)
{
    constexpr int K = 1024;
    constexpr int NKC = K / 32;
    extern __shared__ __nv_bfloat16 sm[];
    const uint32_t smBase = smem_u32(sm);
    const int tid  = threadIdx.x;
    const int wid  = tid >> 5;
    const int lane = tid & 31;
    const int wm   = wid & 3;
    const int wn   = wid >> 2;
    const int m0   = blockIdx.y * 128;
    const int n0   = blockIdx.x * 128;

    const int which = blockIdx.x >> 3;
    const float* bias = which == 0 ? bias0 : (which == 1 ? bias1 : bias2);
    const int col0 = (blockIdx.x & 7) * 128;

    const __nv_bfloat16* gAh = Ah + (long)m0 * K;
    const __nv_bfloat16* gAl = Al + (long)m0 * K;
    const __nv_bfloat16* gBh = Bh + (long)n0 * K;
    const __nv_bfloat16* gBl = Bl + (long)n0 * K;

    float acc[2][8][4];
#pragma unroll
    for (int mt = 0; mt < 2; mt++)
#pragma unroll
        for (int nt = 0; nt < 8; nt++)
#pragma unroll
            for (int j = 0; j < 4; j++) acc[mt][nt][j] = 0.f;

    auto load_stage = [&](int buf, int kc) {
        uint32_t su = smBase + (uint32_t)buf * 4 * GTE * 2;
#pragma unroll
        for (int i = 0; i < 2; i++) {
            int e   = i * 256 + tid;
            int r   = e >> 2;
            int sg  = e & 3;
            long go = (long)r * K + kc * 32 + sg * 8;
            uint32_t so = (uint32_t)(r * GS + sg * 8) * 2;
            cp16(su + so,               gAh + go);
            cp16(su + GTE * 2 + so,     gAl + go);
            cp16(su + 2 * GTE * 2 + so, gBh + go);
            cp16(su + 3 * GTE * 2 + so, gBl + go);
        }
    };

    const int lr = lane >> 2;
    const int lc = (lane & 3) * 2;

    load_stage(0, 0);
    CP_COMMIT();

    for (int kc = 0; kc < NKC; kc++) {
        int p = kc & 1;
        if (kc + 1 < NKC) {
            load_stage(1 - p, kc + 1);
            CP_COMMIT();
            CP_WAIT1();
        } else {
            CP_WAIT0();
        }
        __syncthreads();

        const __nv_bfloat16* sAH = sm + p * 4 * GTE;
        const __nv_bfloat16* sAL = sAH + GTE;
        const __nv_bfloat16* sBH = sAH + 2 * GTE;
        const __nv_bfloat16* sBL = sAH + 3 * GTE;

#pragma unroll
        for (int h = 0; h < 32; h += 16) {
            uint32_t aH[2][4], aL[2][4];
#pragma unroll
            for (int mt = 0; mt < 2; mt++) {
                int rb = (wm * 32 + mt * 16 + lr) * GS + h + lc;
                aH[mt][0] = *reinterpret_cast<const uint32_t*>(sAH + rb);
                aH[mt][1] = *reinterpret_cast<const uint32_t*>(sAH + rb + 8 * GS);
                aH[mt][2] = *reinterpret_cast<const uint32_t*>(sAH + rb + 8);
                aH[mt][3] = *reinterpret_cast<const uint32_t*>(sAH + rb + 8 * GS + 8);
                aL[mt][0] = *reinterpret_cast<const uint32_t*>(sAL + rb);
                aL[mt][1] = *reinterpret_cast<const uint32_t*>(sAL + rb + 8 * GS);
                aL[mt][2] = *reinterpret_cast<const uint32_t*>(sAL + rb + 8);
                aL[mt][3] = *reinterpret_cast<const uint32_t*>(sAL + rb + 8 * GS + 8);
            }
            uint32_t bb[8][2];
#pragma unroll
            for (int nt = 0; nt < 8; nt++) {
                int nb = (wn * 64 + nt * 8 + lr) * GS + h + lc;
                bb[nt][0] = *reinterpret_cast<const uint32_t*>(sBH + nb);
                bb[nt][1] = *reinterpret_cast<const uint32_t*>(sBH + nb + 8);
            }
#pragma unroll
            for (int mt = 0; mt < 2; mt++)
#pragma unroll
                for (int nt = 0; nt < 8; nt++)
                    mma16816(acc[mt][nt], aH[mt][0], aH[mt][1], aH[mt][2], aH[mt][3],
                             bb[nt][0], bb[nt][1]);
#pragma unroll
            for (int mt = 0; mt < 2; mt++)
#pragma unroll
                for (int nt = 0; nt < 8; nt++)
                    mma16816(acc[mt][nt], aL[mt][0], aL[mt][1], aL[mt][2], aL[mt][3],
                             bb[nt][0], bb[nt][1]);
#pragma unroll
            for (int nt = 0; nt < 8; nt++) {
                int nb = (wn * 64 + nt * 8 + lr) * GS + h + lc;
                bb[nt][0] = *reinterpret_cast<const uint32_t*>(sBL + nb);
                bb[nt][1] = *reinterpret_cast<const uint32_t*>(sBL + nb + 8);
            }
#pragma unroll
            for (int mt = 0; mt < 2; mt++)
#pragma unroll
                for (int nt = 0; nt < 8; nt++)
                    mma16816(acc[mt][nt], aH[mt][0], aH[mt][1], aH[mt][2], aH[mt][3],
                             bb[nt][0], bb[nt][1]);
        }
        __syncthreads();
    }

    __nv_bfloat16* Hx = which == 0 ? H0 : (which == 1 ? H1 : H2);
    __nv_bfloat16* Lx = which == 0 ? L0 : (which == 1 ? L1 : L2);

#pragma unroll
    for (int mt = 0; mt < 2; mt++) {
        int row0 = m0 + wm * 32 + mt * 16 + lr;
#pragma unroll
        for (int nt = 0; nt < 8; nt++) {
            int col = col0 + wn * 64 + nt * 8 + lc;
            float2 bv = *reinterpret_cast<const float2*>(bias + col);
            float ox0 = acc[mt][nt][0] + bv.x, oy0 = acc[mt][nt][1] + bv.y;
            float ox1 = acc[mt][nt][2] + bv.x, oy1 = acc[mt][nt][3] + bv.y;
            if (MODE == 0) {
                float2 o0 = {ox0, oy0}, o1 = {ox1, oy1};
                *reinterpret_cast<float2*>(C0 + (long)row0 * 1024 + col)       = o0;
                *reinterpret_cast<float2*>(C0 + (long)(row0 + 8) * 1024 + col) = o1;
            } else {
                uint32_t h0, l0, h1, l1;
                pack_hl(ox0, oy0, h0, l0);
                pack_hl(ox1, oy1, h1, l1);
                *reinterpret_cast<uint32_t*>(Hx + (long)row0 * 1024 + col)       = h0;
                *reinterpret_cast<uint32_t*>(Lx + (long)row0 * 1024 + col)       = l0;
                *reinterpret_cast<uint32_t*>(Hx + (long)(row0 + 8) * 1024 + col) = h1;
                *reinterpret_cast<uint32_t*>(Lx + (long)(row0 + 8) * 1024 + col) = l1;
            }
        }
    }
}

// ---------------- per-head DxD linears -> hi/lo bf16 outputs --------------
static constexpr int PS = 72;
static constexpr int PH_SMEM = 8 * 64 * PS * 2;

__global__ __launch_bounds__(128) void gemm_ph(
    const float* __restrict__ mid,
    const float* __restrict__ wq, const float* __restrict__ wk, const float* __restrict__ wv,
    const float* __restrict__ bq, const float* __restrict__ bk, const float* __restrict__ bv,
    __nv_bfloat16* __restrict__ q1h, __nv_bfloat16* __restrict__ q1l,
    __nv_bfloat16* __restrict__ k1h, __nv_bfloat16* __restrict__ k1l,
    __nv_bfloat16* __restrict__ v1h, __nv_bfloat16* __restrict__ v1l)
{
    extern __shared__ __nv_bfloat16 sp[];
    __nv_bfloat16* Ah = sp + 6 * 64 * PS;
    __nv_bfloat16* Al = sp + 7 * 64 * PS;

    const int tid  = threadIdx.x;
    const int wid  = tid >> 5;
    const int lane = tid & 31;
    const int lr   = lane >> 2;
    const int lc   = (lane & 3) * 2;

    const float* Ws[3] = {wq, wk, wv};
#pragma unroll
    for (int o = 0; o < 3; o++) {
        __nv_bfloat16* Wh = sp + (2 * o)     * 64 * PS;
        __nv_bfloat16* Wl = sp + (2 * o + 1) * 64 * PS;
#pragma unroll
        for (int i = 0; i < 8; i++) {
            int e = i * 128 + tid;
            int r = e >> 4, c = (e & 15) * 4;
            float4 x = *reinterpret_cast<const float4*>(Ws[o] + r * 64 + c);
            split_store4(x, Wh + r * PS + c, Wl + r * PS + c);
        }
    }
    const long abase = (long)blockIdx.x * 64 * 64;
#pragma unroll
    for (int i = 0; i < 8; i++) {
        int e = i * 128 + tid;
        int r = e >> 4, c = (e & 15) * 4;
        float4 x = *reinterpret_cast<const float4*>(mid + abase + r * 64 + c);
        split_store4(x, Ah + r * PS + c, Al + r * PS + c);
    }
    __syncthreads();

    uint32_t aH[4][4], aL[4][4];
#pragma unroll
    for (int ks = 0; ks < 4; ks++) {
        int ab = (wid * 16 + lr) * PS + ks * 16 + lc;
        aH[ks][0] = *reinterpret_cast<const uint32_t*>(Ah + ab);
        aH[ks][1] = *reinterpret_cast<const uint32_t*>(Ah + ab + 8 * PS);
        aH[ks][2] = *reinterpret_cast<const uint32_t*>(Ah + ab + 8);
        aH[ks][3] = *reinterpret_cast<const uint32_t*>(Ah + ab + 8 * PS + 8);
        aL[ks][0] = *reinterpret_cast<const uint32_t*>(Al + ab);
        aL[ks][1] = *reinterpret_cast<const uint32_t*>(Al + ab + 8 * PS);
        aL[ks][2] = *reinterpret_cast<const uint32_t*>(Al + ab + 8);
        aL[ks][3] = *reinterpret_cast<const uint32_t*>(Al + ab + 8 * PS + 8);
    }

    float acc[3][8][4];
#pragma unroll
    for (int o = 0; o < 3; o++)
#pragma unroll
        for (int nt = 0; nt < 8; nt++)
#pragma unroll
            for (int j = 0; j < 4; j++) acc[o][nt][j] = 0.f;

#pragma unroll
    for (int o = 0; o < 3; o++) {
        const __nv_bfloat16* Wh = sp + (2 * o)     * 64 * PS;
        const __nv_bfloat16* Wl = sp + (2 * o + 1) * 64 * PS;
#pragma unroll
        for (int ks = 0; ks < 4; ks++)
#pragma unroll
            for (int nt = 0; nt < 8; nt++) {
                int nb = (nt * 8 + lr) * PS + ks * 16 + lc;
                uint32_t bh0 = *reinterpret_cast<const uint32_t*>(Wh + nb);
                uint32_t bh1 = *reinterpret_cast<const uint32_t*>(Wh + nb + 8);
                uint32_t bl0 = *reinterpret_cast<const uint32_t*>(Wl + nb);
                uint32_t bl1 = *reinterpret_cast<const uint32_t*>(Wl + nb + 8);
                mma16816(acc[o][nt], aH[ks][0], aH[ks][1], aH[ks][2], aH[ks][3], bh0, bh1);
                mma16816(acc[o][nt], aH[ks][0], aH[ks][1], aH[ks][2], aH[ks][3], bl0, bl1);
                mma16816(acc[o][nt], aL[ks][0], aL[ks][1], aL[ks][2], aL[ks][3], bh0, bh1);
            }
    }

    __nv_bfloat16* outsH[3] = {q1h, k1h, v1h};
    __nv_bfloat16* outsL[3] = {q1l, k1l, v1l};
    const float* biases[3] = {bq, bk, bv};
    const long TS = (long)TOT_ * H_;
    int r0 = blockIdx.x * 64 + wid * 16 + lr;
#pragma unroll
    for (int half = 0; half < 2; half++) {
        int r = r0 + half * 8;
        int b = r / (MID_ * NH_);
        int rr = r - b * (MID_ * NH_);
        long off = (long)b * TS + (long)KL_ * H_ + (long)rr * 64;
#pragma unroll
        for (int o = 0; o < 3; o++) {
#pragma unroll
            for (int nt = 0; nt < 8; nt++) {
                int col = nt * 8 + lc;
                float2 bv2 = *reinterpret_cast<const float2*>(biases[o] + col);
                float ox = acc[o][nt][half * 2 + 0] + bv2.x;
                float oy = acc[o][nt][half * 2 + 1] + bv2.y;
                uint32_t hh, ll;
                pack_hl(ox, oy, hh, ll);
                *reinterpret_cast<uint32_t*>(outsH[o] + off + col) = hh;
                *reinterpret_cast<uint32_t*>(outsL[o] + off + col) = ll;
            }
        }
    }
}

// ---------------- Flash attention v2: pre-split bf16 in, cp.async pipelined
static constexpr int FS = 72;
static constexpr int FT = 64 * FS;               // elems per tile
static constexpr int FLASH2_SMEM = 10 * FT * 2;  // Qh,Ql + 2 stages x (Kh,Kl,Vh,Vl)

template<bool HLOUT>
__global__ __launch_bounds__(128) void flash_mma(
    const __nv_bfloat16* __restrict__ Qh, const __nv_bfloat16* __restrict__ Ql,
    const __nv_bfloat16* __restrict__ Kh, const __nv_bfloat16* __restrict__ Kl,
    const __nv_bfloat16* __restrict__ Vh, const __nv_bfloat16* __restrict__ Vl,
    float* __restrict__ Of,
    __nv_bfloat16* __restrict__ Oh, __nv_bfloat16* __restrict__ Ol,
    long bsQ, long bsK, long bsO,
    int klen, float scale)
{
    extern __shared__ __nv_bfloat16 sb[];
    const uint32_t smBase = smem_u32(sb);
    __nv_bfloat16* sQh = sb;
    __nv_bfloat16* sQl = sb + FT;

    const int tid  = threadIdx.x;
    const int wid  = tid >> 5;
    const int lane = tid & 31;
    const int lr   = lane >> 2;
    const int lc   = (lane & 3) * 2;
    const int b    = blockIdx.y >> 4;
    const int h    = blockIdx.y & 15;

    const long qbase = (long)b * bsQ + (long)blockIdx.x * 64 * H_ + h * D_;
    const long kb = (long)b * bsK + h * D_;

    // Q load: 512 cp16 per buffer
    {
        uint32_t suH = smBase;
        uint32_t suL = smBase + FT * 2;
#pragma unroll
        for (int i = 0; i < 4; i++) {
            int e = i * 128 + tid;
            int r = e >> 3, g = e & 7;
            long go = qbase + (long)r * H_ + g * 8;
            uint32_t so = (uint32_t)(r * FS + g * 8) * 2;
            cp16(suH + so, Qh + go);
            cp16(suL + so, Ql + go);
        }
    }

    auto load_kv = [&](int buf, int kt) {
        uint32_t su = smBase + (uint32_t)(2 + buf * 4) * FT * 2;
#pragma unroll
        for (int i = 0; i < 4; i++) {
            int e = i * 128 + tid;
            int r = e >> 3, g = e & 7;
            long go = kb + (long)(kt * 64 + r) * H_ + g * 8;
            uint32_t so = (uint32_t)(r * FS + g * 8) * 2;
            cp16(su + so,              Kh + go);
            cp16(su + FT * 2 + so,     Kl + go);
            cp16(su + 2 * FT * 2 + so, Vh + go);
            cp16(su + 3 * FT * 2 + so, Vl + go);
        }
    };

    float m0 = -1e30f, m1 = -1e30f, li0 = 0.f, li1 = 0.f;
    float o[8][4];
#pragma unroll
    for (int nt = 0; nt < 8; nt++)
#pragma unroll
        for (int j = 0; j < 4; j++) o[nt][j] = 0.f;

    const int ntiles = klen >> 6;

    load_kv(0, 0);
    CP_COMMIT();

    for (int kt = 0; kt < ntiles; kt++) {
        int p = kt & 1;
        if (kt + 1 < ntiles) {
            load_kv(1 - p, kt + 1);
            CP_COMMIT();
            CP_WAIT1();
        } else {
            CP_WAIT0();
        }
        __syncthreads();

        const __nv_bfloat16* sKh = sb + (2 + p * 4) * FT;
        const __nv_bfloat16* sKl = sKh + FT;
        const uint32_t uVh = smBase + (uint32_t)(2 + p * 4 + 2) * FT * 2;
        const uint32_t uVl = uVh + FT * 2;

        // ---- S = Q K^T ----
        float s[8][4];
#pragma unroll
        for (int nt = 0; nt < 8; nt++)
#pragma unroll
            for (int j = 0; j < 4; j++) s[nt][j] = 0.f;

#pragma unroll
        for (int ks = 0; ks < 4; ks++) {
            int ab = (wid * 16 + lr) * FS + ks * 16 + lc;
            uint32_t aH0 = *reinterpret_cast<const uint32_t*>(sQh + ab);
            uint32_t aH1 = *reinterpret_cast<const uint32_t*>(sQh + ab + 8 * FS);
            uint32_t aH2 = *reinterpret_cast<const uint32_t*>(sQh + ab + 8);
            uint32_t aH3 = *reinterpret_cast<const uint32_t*>(sQh + ab + 8 * FS + 8);
            uint32_t aL0 = *reinterpret_cast<const uint32_t*>(sQl + ab);
            uint32_t aL1 = *reinterpret_cast<const uint32_t*>(sQl + ab + 8 * FS);
            uint32_t aL2 = *reinterpret_cast<const uint32_t*>(sQl + ab + 8);
            uint32_t aL3 = *reinterpret_cast<const uint32_t*>(sQl + ab + 8 * FS + 8);
#pragma unroll
            for (int nt = 0; nt < 8; nt++) {
                int nb = (nt * 8 + lr) * FS + ks * 16 + lc;
                uint32_t bh0 = *reinterpret_cast<const uint32_t*>(sKh + nb);
                uint32_t bh1 = *reinterpret_cast<const uint32_t*>(sKh + nb + 8);
                uint32_t bl0 = *reinterpret_cast<const uint32_t*>(sKl + nb);
                uint32_t bl1 = *reinterpret_cast<const uint32_t*>(sKl + nb + 8);
                mma16816(s[nt], aH0, aH1, aH2, aH3, bh0, bh1);
                mma16816(s[nt], aH0, aH1, aH2, aH3, bl0, bl1);
                mma16816(s[nt], aL0, aL1, aL2, aL3, bh0, bh1);
            }
        }

        // ---- online softmax ----
        float rm0 = -1e30f, rm1 = -1e30f;
#pragma unroll
        for (int nt = 0; nt < 8; nt++) {
            rm0 = fmaxf(rm0, fmaxf(s[nt][0], s[nt][1]));
            rm1 = fmaxf(rm1, fmaxf(s[nt][2], s[nt][3]));
        }
        rm0 *= scale; rm1 *= scale;
#pragma unroll
        for (int off = 1; off <= 2; off <<= 1) {
            rm0 = fmaxf(rm0, __shfl_xor_sync(0xffffffffu, rm0, off));
            rm1 = fmaxf(rm1, __shfl_xor_sync(0xffffffffu, rm1, off));
        }
        float mn0 = fmaxf(m0, rm0), mn1 = fmaxf(m1, rm1);
        float al0 = __expf(m0 - mn0), al1 = __expf(m1 - mn1);

        float rs0 = 0.f, rs1 = 0.f;
#pragma unroll
        for (int nt = 0; nt < 8; nt++) {
            float p0 = __expf(fmaf(s[nt][0], scale, -mn0));
            float p1 = __expf(fmaf(s[nt][1], scale, -mn0));
            float p2 = __expf(fmaf(s[nt][2], scale, -mn1));
            float p3 = __expf(fmaf(s[nt][3], scale, -mn1));
            rs0 += p0 + p1; rs1 += p2 + p3;
            s[nt][0] = p0; s[nt][1] = p1; s[nt][2] = p2; s[nt][3] = p3;
        }
#pragma unroll
        for (int off = 1; off <= 2; off <<= 1) {
            rs0 += __shfl_xor_sync(0xffffffffu, rs0, off);
            rs1 += __shfl_xor_sync(0xffffffffu, rs1, off);
        }
        li0 = li0 * al0 + rs0;
        li1 = li1 * al1 + rs1;
#pragma unroll
        for (int nt = 0; nt < 8; nt++) {
            o[nt][0] *= al0; o[nt][1] *= al0;
            o[nt][2] *= al1; o[nt][3] *= al1;
        }
        m0 = mn0; m1 = mn1;

        // ---- O += P V ----
#pragma unroll
        for (int ks = 0; ks < 4; ks++) {
            int t0 = 2 * ks, t1 = 2 * ks + 1;
            uint32_t a0h, a0l, a1h, a1l, a2h, a2l, a3h, a3l;
            pack_hl(s[t0][0], s[t0][1], a0h, a0l);
            pack_hl(s[t0][2], s[t0][3], a1h, a1l);
            pack_hl(s[t1][0], s[t1][1], a2h, a2l);
            pack_hl(s[t1][2], s[t1][3], a3h, a3l);

            int key  = ks * 16 + (lane & 15);
            int dsub = (lane >> 4) << 3;
#pragma unroll
            for (int dblk = 0; dblk < 4; dblk++) {
                uint32_t off16 = (uint32_t)(key * FS + dblk * 16 + dsub) * 2;
                uint32_t vh0, vh1, vh2, vh3, vl0, vl1, vl2, vl3;
                ldmx4t(vh0, vh1, vh2, vh3, uVh + off16);
                ldmx4t(vl0, vl1, vl2, vl3, uVl + off16);
                mma16816(o[2 * dblk],     a0h, a1h, a2h, a3h, vh0, vh1);
                mma16816(o[2 * dblk],     a0h, a1h, a2h, a3h, vl0, vl1);
                mma16816(o[2 * dblk],     a0l, a1l, a2l, a3l, vh0, vh1);
                mma16816(o[2 * dblk + 1], a0h, a1h, a2h, a3h, vh2, vh3);
                mma16816(o[2 * dblk + 1], a0h, a1h, a2h, a3h, vl2, vl3);
                mma16816(o[2 * dblk + 1], a0l, a1l, a2l, a3l, vh2, vh3);
            }
        }
        __syncthreads();
    }

    const long obase = (long)b * bsO + (long)blockIdx.x * 64 * H_ + h * D_;
    float inv0 = 1.f / li0, inv1 = 1.f / li1;
    int row0 = wid * 16 + lr;
#pragma unroll
    for (int nt = 0; nt < 8; nt++) {
        int col = nt * 8 + lc;
        float x0 = o[nt][0] * inv0, y0 = o[nt][1] * inv0;
        float x1 = o[nt][2] * inv1, y1 = o[nt][3] * inv1;
        if (!HLOUT) {
            float2 o0 = {x0, y0}, o1 = {x1, y1};
            *reinterpret_cast<float2*>(Of + obase + (long)row0 * H_ + col)       = o0;
            *reinterpret_cast<float2*>(Of + obase + (long)(row0 + 8) * H_ + col) = o1;
        } else {
            uint32_t h0, l0, h1, l1;
            pack_hl(x0, y0, h0, l0);
            pack_hl(x1, y1, h1, l1);
            *reinterpret_cast<uint32_t*>(Oh + obase + (long)row0 * H_ + col)       = h0;
            *reinterpret_cast<uint32_t*>(Ol + obase + (long)row0 * H_ + col)       = l0;
            *reinterpret_cast<uint32_t*>(Oh + obase + (long)(row0 + 8) * H_ + col) = h1;
            *reinterpret_cast<uint32_t*>(Ol + obase + (long)(row0 + 8) * H_ + col) = l1;
        }
    }
}

// ---------------- task-slice copies (bf16 hi/lo, exact) ----------------
__global__ __launch_bounds__(256) void copy_task_hl(
    const __nv_bfloat16* __restrict__ q0h, const __nv_bfloat16* __restrict__ q0l,
    const __nv_bfloat16* __restrict__ k0h, const __nv_bfloat16* __restrict__ k0l,
    __nv_bfloat16* __restrict__ q1h, __nv_bfloat16* __restrict__ q1l,
    __nv_bfloat16* __restrict__ k1h, __nv_bfloat16* __restrict__ k1l,
    __nv_bfloat16* __restrict__ v1h, __nv_bfloat16* __restrict__ v1l)
{
    int idx = blockIdx.x * blockDim.x + threadIdx.x;
    if (idx >= B_ * KL_ * H_ / 8) return;
    long e = (long)idx * 8;
    int b = (int)(e / (KL_ * H_));
    long r = e - (long)b * (KL_ * H_);
    long src = (long)b * TOT_ * H_ + (long)MID_ * H_ + r;
    long dst = (long)b * TOT_ * H_ + r;
    uint4 qh = *reinterpret_cast<const uint4*>(q0h + src);
    uint4 ql = *reinterpret_cast<const uint4*>(q0l + src);
    *reinterpret_cast<uint4*>(q1h + dst) = qh;
    *reinterpret_cast<uint4*>(q1l + dst) = ql;
    *reinterpret_cast<uint4*>(v1h + dst) = qh;
    *reinterpret_cast<uint4*>(v1l + dst) = ql;
    *reinterpret_cast<uint4*>(k1h + dst) = *reinterpret_cast<const uint4*>(k0h + src);
    *reinterpret_cast<uint4*>(k1l + dst) = *reinterpret_cast<const uint4*>(k0l + src);
}

// ---------------- launch ----------------
extern "C" void kernel_launch(void* const* d_in, const int* in_sizes, int n_in,
                              void* d_out, int out_size)
{
    const float* vis  = (const float*)d_in[0];
    const float* txt  = (const float*)d_in[1];
    const float* task = (const float*)d_in[2];
    const float* wq0  = (const float*)d_in[3];
    const float* bq0  = (const float*)d_in[4];
    const float* wk0  = (const float*)d_in[5];
    const float* bk0  = (const float*)d_in[6];
    const float* wv0  = (const float*)d_in[7];
    const float* bv0  = (const float*)d_in[8];
    const float* wq1  = (const float*)d_in[9];
    const float* bq1  = (const float*)d_in[10];
    const float* wk1  = (const float*)d_in[11];
    const float* bk1  = (const float*)d_in[12];
    const float* wv1  = (const float*)d_in[13];
    const float* bv1  = (const float*)d_in[14];
    const float* wo   = (const float*)d_in[15];
    const float* bo   = (const float*)d_in[16];
    float* out = (float*)d_out;

    float* mid;
    cudaGetSymbolAddress((void**)&mid, g_mid);

    __nv_bfloat16 *xh, *xl, *aoh, *aol, *wh, *wl;
    cudaGetSymbolAddress((void**)&xh,  g_xh);
    cudaGetSymbolAddress((void**)&xl,  g_xl);
    cudaGetSymbolAddress((void**)&aoh, g_aoh);
    cudaGetSymbolAddress((void**)&aol, g_aol);
    cudaGetSymbolAddress((void**)&wh,  g_wh);
    cudaGetSymbolAddress((void**)&wl,  g_wl);

    __nv_bfloat16 *q0h,*q0l,*k0h,*k0l,*v0h,*v0l,*q1h,*q1l,*k1h,*k1l,*v1h,*v1l;
    cudaGetSymbolAddress((void**)&q0h, g_q0h); cudaGetSymbolAddress((void**)&q0l, g_q0l);
    cudaGetSymbolAddress((void**)&k0h, g_k0h); cudaGetSymbolAddress((void**)&k0l, g_k0l);
    cudaGetSymbolAddress((void**)&v0h, g_v0h); cudaGetSymbolAddress((void**)&v0l, g_v0l);
    cudaGetSymbolAddress((void**)&q1h, g_q1h); cudaGetSymbolAddress((void**)&q1l, g_q1l);
    cudaGetSymbolAddress((void**)&k1h, g_k1h); cudaGetSymbolAddress((void**)&k1l, g_k1l);
    cudaGetSymbolAddress((void**)&v1h, g_v1h); cudaGetSymbolAddress((void**)&v1l, g_v1l);

    cudaFuncSetAttribute(gemm_mma<0>, cudaFuncAttributeMaxDynamicSharedMemorySize, GMMA_SMEM);
    cudaFuncSetAttribute(gemm_mma<1>, cudaFuncAttributeMaxDynamicSharedMemorySize, GMMA_SMEM);
    cudaFuncSetAttribute(flash_mma<false>, cudaFuncAttributeMaxDynamicSharedMemorySize, FLASH2_SMEM);
    cudaFuncSetAttribute(flash_mma<true>,  cudaFuncAttributeMaxDynamicSharedMemorySize, FLASH2_SMEM);
    cudaFuncSetAttribute(gemm_ph,   cudaFuncAttributeMaxDynamicSharedMemorySize, PH_SMEM);

    const dim3 blk(256);
    const long TS = (long)TOT_ * H_;
    const long MS = (long)MID_ * H_;
    const float scale = 1.0f / 64.0f;
    const long WN4 = (long)H_ * H_ / 4;

    // 0) pack inputs to hi/lo bf16
    pack_gather_hilo<<<ROWS_ * H_ / 1024, blk>>>(vis, txt, task, xh, xl);
    pack_hilo<<<(int)(WN4 / 256), blk>>>(wq0, wh + 0L * H_ * H_, wl + 0L * H_ * H_, WN4);
    pack_hilo<<<(int)(WN4 / 256), blk>>>(wk0, wh + 1L * H_ * H_, wl + 1L * H_ * H_, WN4);
    pack_hilo<<<(int)(WN4 / 256), blk>>>(wv0, wh + 2L * H_ * H_, wl + 2L * H_ * H_, WN4);
    pack_hilo<<<(int)(WN4 / 256), blk>>>(wo,  wh + 3L * H_ * H_, wl + 3L * H_ * H_, WN4);

    // 1) fused QKV projection -> hi/lo bf16 q0/k0/v0
    {
        dim3 g(3 * H_ / 128, ROWS_ / 128);
        gemm_mma<1><<<g, blk, GMMA_SMEM>>>(xh, xl, wh, wl, bq0, bk0, bv0,
                                           nullptr, q0h, q0l, k0h, k0l, v0h, v0l);
    }

    // 2) cross attentions -> mid (fp32)
    flash_mma<false><<<dim3(VL_ / 64, B_ * NH_), 128, FLASH2_SMEM>>>(
        q0h, q0l, k0h + (long)VL_ * H_, k0l + (long)VL_ * H_,
        v0h + (long)VL_ * H_, v0l + (long)VL_ * H_,
        mid, nullptr, nullptr, TS, TS, MS, TL_, scale);
    flash_mma<false><<<dim3(TL_ / 64, B_ * NH_), 128, FLASH2_SMEM>>>(
        q0h + (long)VL_ * H_, q0l + (long)VL_ * H_, k0h, k0l, v0h, v0l,
        mid + (long)VL_ * H_, nullptr, nullptr, TS, TS, MS, VL_, scale);

    // 3) per-head D x D linears -> hi/lo q1/k1/v1 tokens [64..2560)
    gemm_ph<<<(B_ * MID_ * NH_) / 64, 128, PH_SMEM>>>(
        mid, wq1, wk1, wv1, bq1, bk1, bv1, q1h, q1l, k1h, k1l, v1h, v1l);

    // 4) task slices (exact bf16 pair copies; v1 <- q0 slice)
    copy_task_hl<<<(B_ * KL_ * H_ / 8 + 255) / 256, blk>>>(
        q0h, q0l, k0h, k0l, q1h, q1l, k1h, k1l, v1h, v1l);

    // 5) full attention -> hi/lo ao
    flash_mma<true><<<dim3(TOT_ / 64, B_ * NH_), 128, FLASH2_SMEM>>>(
        q1h, q1l, k1h, k1l, v1h, v1l,
        nullptr, aoh, aol, TS, TS, TS, TOT_, scale);

    // 6) output projection (fp32 out)
    {
        dim3 g(H_ / 128, ROWS_ / 128);
        gemm_mma<0><<<g, blk, GMMA_SMEM>>>(aoh, aol, wh + 3L*H_*H_, wl + 3L*H_*H_,
                                           bo, bo, bo, out,
                                           nullptr, nullptr, nullptr, nullptr, nullptr, nullptr);
    }
}